// round 1
// baseline (speedup 1.0000x reference)
#include <cuda_runtime.h>
#include <math.h>

#define BB 4
#define CC 256
#define NHEAD 8
#define DHEAD 32
#define MF 128
#define NN 9216
#define TT (BB*NN)   /* 36864 */

#define NRM       0.4204482076268573f     /* 32^-0.25 */
#define HALF_NRM2 0.08838834764831845f    /* 0.5 * 32^-0.5 */
#define RATIO     0.08838834764831845f    /* 128^-0.5 */
#define EPSF      1e-4f

/* ------------------------------------------------------------------ */
/* scratch (static device memory: allowed; no runtime allocation)      */
/* ------------------------------------------------------------------ */
__device__ float g_q[(size_t)TT*CC];
__device__ float g_k[(size_t)TT*CC];
__device__ float g_v[(size_t)TT*CC];
__device__ float g_attn[(size_t)TT*CC];
__device__ float g_kdashT[(size_t)32*MF*NN];   /* [bh][m][n] */
__device__ float g_kdiag[32*NN];
__device__ float g_kmax[32];
__device__ float g_ctx[32*MF*33];              /* [bh][m][j], j=32 is k_sum */
__device__ float g_Wc[CC*CC];
__device__ float g_bc[CC];

__device__ __forceinline__ void atomicMaxF(float* a, float v){
    int old = __float_as_int(*a);
    while (__int_as_float(old) < v){
        int cur = atomicCAS((int*)a, old, __float_as_int(v));
        if (cur == old) break;
        old = cur;
    }
}

/* ------------------------------------------------------------------ */
/* K0: fold wo + 1x1 conv into one weight, and init scratch            */
/* ------------------------------------------------------------------ */
__global__ void k_prep(const float* __restrict__ wo, const float* __restrict__ bo,
                       const float* __restrict__ wp, const float* __restrict__ bp){
    int o2 = blockIdx.x;
    int c  = threadIdx.x;
    float s = 0.f;
    for (int o = 0; o < 256; o++) s += wp[o2*256 + o] * wo[o*256 + c];
    g_Wc[o2*256 + c] = s;
    if (c == 0){
        float sb = 0.f;
        for (int o = 0; o < 256; o++) sb += wp[o2*256 + o] * bo[o];
        g_bc[o2] = sb + bp[o2];
    }
}

__global__ void k_init(){
    int i = blockIdx.x*blockDim.x + threadIdx.x;
    if (i < 32*MF*33) g_ctx[i] = 0.f;
    if (i < 32) g_kmax[i] = -1e30f;
}

/* ------------------------------------------------------------------ */
/* K1: QKV GEMM. A = x^T (x stored c-major), B = wq/wk/wv              */
/* C[t][o] -> g_q/g_k/g_v[t*256 + o]                                   */
/* grid (288, 6), 256 thr, tile 128x128x8, micro 8x8                   */
/* ------------------------------------------------------------------ */
__global__ void __launch_bounds__(256) k_qkv(const float* __restrict__ x,
        const float* __restrict__ wq, const float* __restrict__ wk,
        const float* __restrict__ wv){
    __shared__ float As[8][128];
    __shared__ float Bs[8][128];
    int tid = threadIdx.x;
    int t0  = blockIdx.x * 128;
    int b   = t0 / NN;
    int tl0 = t0 % NN;
    int oc  = blockIdx.y;                       /* 0..5 */
    const float* W = (oc < 2) ? wq : (oc < 4 ? wk : wv);
    float* dst     = (oc < 2) ? g_q : (oc < 4 ? g_k : g_v);
    int or0 = (oc & 1) * 128;

    int a_c = tid >> 5, a_t = (tid & 31) * 4;
    int b_o = tid >> 1, b_c = (tid & 1) * 4;
    int tx = tid & 15, ty = tid >> 4;

    float acc[8][8];
#pragma unroll
    for (int i = 0; i < 8; i++)
#pragma unroll
        for (int j = 0; j < 8; j++) acc[i][j] = 0.f;

    for (int k0 = 0; k0 < 256; k0 += 8){
        float4 av = *(const float4*)&x[((size_t)(b*256 + k0 + a_c))*NN + tl0 + a_t];
        *(float4*)&As[a_c][a_t] = av;
        float4 bv = *(const float4*)&W[(or0 + b_o)*256 + k0 + b_c];
        Bs[b_c+0][b_o] = bv.x; Bs[b_c+1][b_o] = bv.y;
        Bs[b_c+2][b_o] = bv.z; Bs[b_c+3][b_o] = bv.w;
        __syncthreads();
#pragma unroll
        for (int kk = 0; kk < 8; kk++){
            float a[8], bb[8];
#pragma unroll
            for (int i = 0; i < 8; i++) a[i]  = As[kk][ty*8 + i];
#pragma unroll
            for (int j = 0; j < 8; j++) bb[j] = Bs[kk][tx*8 + j];
#pragma unroll
            for (int i = 0; i < 8; i++)
#pragma unroll
                for (int j = 0; j < 8; j++) acc[i][j] += a[i]*bb[j];
        }
        __syncthreads();
    }
    int trow  = t0 + ty*8;
    int obase = or0 + tx*8;
#pragma unroll
    for (int i = 0; i < 8; i++){
        float4 v0 = make_float4(acc[i][0], acc[i][1], acc[i][2], acc[i][3]);
        float4 v1 = make_float4(acc[i][4], acc[i][5], acc[i][6], acc[i][7]);
        *(float4*)&dst[(size_t)(trow + i)*256 + obase]     = v0;
        *(float4*)&dst[(size_t)(trow + i)*256 + obase + 4] = v1;
    }
}

/* ------------------------------------------------------------------ */
/* K2: key dash + per-(b,h) global max + diag.                         */
/* grid (36, 32), 256 thr, one thread per token row                    */
/* ------------------------------------------------------------------ */
__global__ void __launch_bounds__(256) k_kdash(const float* __restrict__ proj){
    __shared__ float4 projs[1024];   /* [m][8] float4 = 128x32 */
    __shared__ float red[256];
    int bh = blockIdx.y;
    int n  = blockIdx.x * 256 + threadIdx.x;
    int b = bh >> 3, h = bh & 7;
    for (int i = threadIdx.x; i < 1024; i += 256)
        projs[i] = ((const float4*)proj)[i];
    __syncthreads();

    const float4* kr4 = (const float4*)&g_k[((size_t)b*NN + n)*256 + h*32];
    float4 kr[8];
#pragma unroll
    for (int i = 0; i < 8; i++) kr[i] = kr4[i];
    float sq = 0.f;
#pragma unroll
    for (int i = 0; i < 8; i++)
        sq += kr[i].x*kr[i].x + kr[i].y*kr[i].y + kr[i].z*kr[i].z + kr[i].w*kr[i].w;
    g_kdiag[bh*NN + n] = HALF_NRM2 * sq;

    float mx = -1e30f;
    size_t base = ((size_t)bh*MF)*NN + n;
    for (int m = 0; m < MF; m++){
        float s = 0.f;
        const float4* pm = &projs[m*8];
#pragma unroll
        for (int i = 0; i < 8; i++){
            float4 p = pm[i];
            s += kr[i].x*p.x + kr[i].y*p.y + kr[i].z*p.z + kr[i].w*p.w;
        }
        s *= NRM;
        g_kdashT[base + (size_t)m*NN] = s;
        mx = fmaxf(mx, s);
    }
    red[threadIdx.x] = mx;
    __syncthreads();
    for (int s = 128; s > 0; s >>= 1){
        if (threadIdx.x < (unsigned)s)
            red[threadIdx.x] = fmaxf(red[threadIdx.x], red[threadIdx.x + s]);
        __syncthreads();
    }
    if (threadIdx.x == 0) atomicMaxF(&g_kmax[bh], red[0]);
}

/* ------------------------------------------------------------------ */
/* K3: ctx = kp^T @ [v | 1]  (accumulates k_sum as column 32)          */
/* grid (16, 32), 256 thr. Each block: 9 tiles of 64 rows.             */
/* thread (m, js): js warp-uniform, m = warp-group*32 + lane           */
/* ------------------------------------------------------------------ */
#define CTX_SPLITS 16
#define CTX_TILES  9          /* 16*9*64 = 9216 */
__global__ void __launch_bounds__(256) k_ctx(){
    __shared__ float kps[128][65];
    __shared__ float vs[64][36];
    int bh = blockIdx.y;
    int sp = blockIdx.x;
    int b = bh >> 3, h = bh & 7;
    int tid = threadIdx.x;
    int js = (tid >> 5) & 1;
    int m  = ((tid >> 6) << 5) | (tid & 31);
    int jbase = js * 16;
    float mk = g_kmax[bh];

    float acc[17];
#pragma unroll
    for (int i = 0; i < 17; i++) acc[i] = 0.f;

    for (int it = 0; it < CTX_TILES; it++){
        int n0 = sp*(CTX_TILES*64) + it*64;
        /* kp tile: 128 x 64, exp on load */
#pragma unroll
        for (int i = 0; i < 32; i++){
            int lin = i*256 + tid;
            int mm = lin >> 6, nn = lin & 63;
            float d  = g_kdashT[((size_t)bh*MF + mm)*NN + n0 + nn];
            float dg = g_kdiag[bh*NN + n0 + nn];
            kps[mm][nn] = RATIO * (__expf(d - dg - mk) + EPSF);
        }
        /* v tile: 64 x 32 (+ ones column) */
#pragma unroll
        for (int i = 0; i < 8; i++){
            int lin = i*256 + tid;
            int nn = lin >> 5, jj = lin & 31;
            vs[nn][jj] = g_v[((size_t)b*NN + n0 + nn)*256 + h*32 + jj];
        }
        if (tid < 64) vs[tid][32] = 1.0f;
        __syncthreads();

        for (int n = 0; n < 64; n++){
            float kp = kps[m][n];
#pragma unroll
            for (int q = 0; q < 4; q++){
                float4 v4 = *(const float4*)&vs[n][jbase + q*4];
                acc[q*4+0] += kp*v4.x; acc[q*4+1] += kp*v4.y;
                acc[q*4+2] += kp*v4.z; acc[q*4+3] += kp*v4.w;
            }
            if (js == 0) acc[16] += kp * vs[n][32];
        }
        __syncthreads();
    }
    size_t cb = ((size_t)bh*MF + m)*33;
#pragma unroll
    for (int q = 0; q < 16; q++) atomicAdd(&g_ctx[cb + jbase + q], acc[q]);
    if (js == 0) atomicAdd(&g_ctx[cb + 32], acc[16]);
}

/* ------------------------------------------------------------------ */
/* K4: q features + out = (qp @ ctx) * d_inv. One thread per token.    */
/* grid (36, 32), 256 thr.                                             */
/* ------------------------------------------------------------------ */
__global__ void __launch_bounds__(256) k_qattn(const float* __restrict__ proj){
    __shared__ float4 projs[1024];      /* 128 x 32 */
    __shared__ float  ctxs[128*36];     /* [m][36], 33 used */
    int bh = blockIdx.y;
    int n  = blockIdx.x*256 + threadIdx.x;
    int b = bh >> 3, h = bh & 7;
    for (int i = threadIdx.x; i < 1024; i += 256)
        projs[i] = ((const float4*)proj)[i];
    for (int i = threadIdx.x; i < 128*33; i += 256){
        int mm = i / 33, jj = i % 33;
        ctxs[mm*36 + jj] = g_ctx[((size_t)bh*MF + mm)*33 + jj];
    }
    __syncthreads();

    const float4* src = (const float4*)&g_q[((size_t)b*NN + n)*256 + h*32];
    float4 qr[8];
#pragma unroll
    for (int i = 0; i < 8; i++) qr[i] = src[i];
    float sq = 0.f;
#pragma unroll
    for (int i = 0; i < 8; i++)
        sq += qr[i].x*qr[i].x + qr[i].y*qr[i].y + qr[i].z*qr[i].z + qr[i].w*qr[i].w;
    float diag = HALF_NRM2 * sq;

    /* pass 1: row max of dash */
    float mx = -1e30f;
    for (int m = 0; m < MF; m++){
        float s = 0.f;
        const float4* pm = &projs[m*8];
#pragma unroll
        for (int i = 0; i < 8; i++){
            float4 p = pm[i];
            s += qr[i].x*p.x + qr[i].y*p.y + qr[i].z*p.z + qr[i].w*p.w;
        }
        mx = fmaxf(mx, s * NRM);
    }
    /* pass 2: exp + accumulate against ctx */
    float4 a4[8];
#pragma unroll
    for (int i = 0; i < 8; i++) a4[i] = make_float4(0.f,0.f,0.f,0.f);
    float aden = 0.f;
    for (int m = 0; m < MF; m++){
        float s = 0.f;
        const float4* pm = &projs[m*8];
#pragma unroll
        for (int i = 0; i < 8; i++){
            float4 p = pm[i];
            s += qr[i].x*p.x + qr[i].y*p.y + qr[i].z*p.z + qr[i].w*p.w;
        }
        float p = RATIO * (__expf(s*NRM - diag - mx) + EPSF);
        const float* cr = &ctxs[m*36];
#pragma unroll
        for (int i = 0; i < 8; i++){
            float4 c = *(const float4*)&cr[i*4];
            a4[i].x += p*c.x; a4[i].y += p*c.y; a4[i].z += p*c.z; a4[i].w += p*c.w;
        }
        aden += p * cr[32];
    }
    float inv = 1.0f / aden;
    float4* dst = (float4*)&g_attn[((size_t)b*NN + n)*256 + h*32];
#pragma unroll
    for (int i = 0; i < 8; i++)
        dst[i] = make_float4(a4[i].x*inv, a4[i].y*inv, a4[i].z*inv, a4[i].w*inv);
}

/* ------------------------------------------------------------------ */
/* K5: out[b][o][n] = attn[b][n][:] @ Wc[o][:] + bc[o]                 */
/* grid (288, 2), 256 thr, tile 128x128x8, micro 8x8, transposed store */
/* ------------------------------------------------------------------ */
__global__ void __launch_bounds__(256) k_final(float* __restrict__ out){
    __shared__ float As[8][128];
    __shared__ float Bs[8][128];
    int tid = threadIdx.x;
    int t0  = blockIdx.x * 128;
    int b   = t0 / NN;
    int tl0 = t0 % NN;
    int o0  = blockIdx.y * 128;

    int at = tid >> 1, ac = (tid & 1) * 4;
    int bo_ = tid >> 1, bc = (tid & 1) * 4;
    int tx = tid & 15, ty = tid >> 4;

    float acc[8][8];
#pragma unroll
    for (int i = 0; i < 8; i++)
#pragma unroll
        for (int j = 0; j < 8; j++) acc[i][j] = 0.f;

    for (int k0 = 0; k0 < 256; k0 += 8){
        float4 av = *(const float4*)&g_attn[(size_t)(t0 + at)*256 + k0 + ac];
        As[ac+0][at] = av.x; As[ac+1][at] = av.y;
        As[ac+2][at] = av.z; As[ac+3][at] = av.w;
        float4 bv = *(const float4*)&g_Wc[(o0 + bo_)*256 + k0 + bc];
        Bs[bc+0][bo_] = bv.x; Bs[bc+1][bo_] = bv.y;
        Bs[bc+2][bo_] = bv.z; Bs[bc+3][bo_] = bv.w;
        __syncthreads();
#pragma unroll
        for (int kk = 0; kk < 8; kk++){
            float a[8], bb[8];
#pragma unroll
            for (int i = 0; i < 8; i++) a[i]  = As[kk][ty*8 + i];
#pragma unroll
            for (int j = 0; j < 8; j++) bb[j] = Bs[kk][tx*8 + j];
#pragma unroll
            for (int i = 0; i < 8; i++)
#pragma unroll
                for (int j = 0; j < 8; j++) acc[i][j] += a[i]*bb[j];
        }
        __syncthreads();
    }
#pragma unroll
    for (int j = 0; j < 8; j++){
        int o = o0 + tx*8 + j;
        float bias = g_bc[o];
        float4 v0 = make_float4(acc[0][j]+bias, acc[1][j]+bias, acc[2][j]+bias, acc[3][j]+bias);
        float4 v1 = make_float4(acc[4][j]+bias, acc[5][j]+bias, acc[6][j]+bias, acc[7][j]+bias);
        size_t base = ((size_t)b*256 + o)*NN + tl0 + ty*8;
        *(float4*)&out[base]     = v0;
        *(float4*)&out[base + 4] = v1;
    }
}

/* ------------------------------------------------------------------ */
extern "C" void kernel_launch(void* const* d_in, const int* in_sizes, int n_in,
                              void* d_out, int out_size){
    const float* x    = (const float*)d_in[0];
    const float* wq   = (const float*)d_in[1];
    const float* wk   = (const float*)d_in[2];
    const float* wv   = (const float*)d_in[3];
    const float* wo   = (const float*)d_in[4];
    const float* bo   = (const float*)d_in[5];
    const float* proj = (const float*)d_in[6];
    const float* wp   = (const float*)d_in[7];
    const float* bp   = (const float*)d_in[8];
    float* out = (float*)d_out;

    k_prep<<<256, 256>>>(wo, bo, wp, bp);
    k_init<<<(32*MF*33 + 255)/256, 256>>>();
    k_qkv<<<dim3(TT/128, 6), 256>>>(x, wq, wk, wv);
    k_kdash<<<dim3(NN/256, 32), 256>>>(proj);
    k_ctx<<<dim3(CTX_SPLITS, 32), 256>>>();
    k_qattn<<<dim3(NN/256, 32), 256>>>(proj);
    k_final<<<dim3(TT/128, 2), 256>>>(out);
}

// round 2
// speedup vs baseline: 1.1217x; 1.1217x over previous
#include <cuda_runtime.h>
#include <math.h>

#define BB 4
#define CC 256
#define NHEAD 8
#define DHEAD 32
#define MF 128
#define NN 9216
#define TT (BB*NN)   /* 36864 */

#define NRM       0.4204482076268573f     /* 32^-0.25 */
#define HALF_NRM2 0.08838834764831845f    /* 0.5 * 32^-0.5 */
#define RATIO     0.08838834764831845f    /* 128^-0.5 */
#define EPSF      1e-4f

typedef unsigned long long u64;

/* ---------------- f32x2 (FFMA2) helpers ---------------- */
__device__ __forceinline__ u64 pack2(float lo, float hi){
    u64 r; asm("mov.b64 %0, {%1,%2};" : "=l"(r) : "f"(lo), "f"(hi)); return r;
}
__device__ __forceinline__ u64 dup2(float v){
    u64 r; asm("mov.b64 %0, {%1,%1};" : "=l"(r) : "f"(v)); return r;
}
__device__ __forceinline__ void fma2(u64 &c, u64 a, u64 b){
    asm("fma.rn.f32x2 %0, %1, %2, %0;" : "+l"(c) : "l"(a), "l"(b));
}
__device__ __forceinline__ float2 unpk(u64 v){
    float2 r; asm("mov.b64 {%0,%1}, %2;" : "=f"(r.x), "=f"(r.y) : "l"(v)); return r;
}

/* ---------------- scratch ---------------- */
__device__ float g_q[(size_t)TT*CC];
__device__ float g_k[(size_t)TT*CC];
__device__ float g_v[(size_t)TT*CC];
__device__ float g_attn[(size_t)TT*CC];
__device__ float g_kdashT[(size_t)32*MF*NN];   /* [bh][m][n] */
__device__ float g_kdiag[32*NN];
__device__ float g_kmax[32];
__device__ float g_ctx[32*MF*33];              /* [bh][m][j], j=32 is k_sum */
__device__ float g_Wc[CC*CC];
__device__ float g_bc[CC];

__device__ __forceinline__ void atomicMaxF(float* a, float v){
    int old = __float_as_int(*a);
    while (__int_as_float(old) < v){
        int cur = atomicCAS((int*)a, old, __float_as_int(v));
        if (cur == old) break;
        old = cur;
    }
}

/* ------------------------------------------------------------------ */
/* K0: fold wo + 1x1 conv into one weight                              */
/* ------------------------------------------------------------------ */
__global__ void k_prep(const float* __restrict__ wo, const float* __restrict__ bo,
                       const float* __restrict__ wp, const float* __restrict__ bp){
    int o2 = blockIdx.x;
    int c  = threadIdx.x;
    float s = 0.f;
    for (int o = 0; o < 256; o++) s += wp[o2*256 + o] * wo[o*256 + c];
    g_Wc[o2*256 + c] = s;
    if (c == 0){
        float sb = 0.f;
        for (int o = 0; o < 256; o++) sb += wp[o2*256 + o] * bo[o];
        g_bc[o2] = sb + bp[o2];
    }
}

__global__ void k_init(){
    int i = blockIdx.x*blockDim.x + threadIdx.x;
    if (i < 32*MF*33) g_ctx[i] = 0.f;
    if (i < 32) g_kmax[i] = -1e30f;
}

/* ------------------------------------------------------------------ */
/* K1: QKV GEMM (f32x2 micro-kernel)                                   */
/* ------------------------------------------------------------------ */
__global__ void __launch_bounds__(256) k_qkv(const float* __restrict__ x,
        const float* __restrict__ wq, const float* __restrict__ wk,
        const float* __restrict__ wv){
    __shared__ float As[8][128];
    __shared__ float Bs[8][128];
    int tid = threadIdx.x;
    int t0  = blockIdx.x * 128;
    int b   = t0 / NN;
    int tl0 = t0 % NN;
    int oc  = blockIdx.y;
    const float* W = (oc < 2) ? wq : (oc < 4 ? wk : wv);
    float* dst     = (oc < 2) ? g_q : (oc < 4 ? g_k : g_v);
    int or0 = (oc & 1) * 128;

    int a_c = tid >> 5, a_t = (tid & 31) * 4;
    int b_o = tid >> 1, b_c = (tid & 1) * 4;
    int tx = tid & 15, ty = tid >> 4;

    u64 acc[8][4];
#pragma unroll
    for (int i = 0; i < 8; i++)
#pragma unroll
        for (int j = 0; j < 4; j++) acc[i][j] = 0ULL;

    for (int k0 = 0; k0 < 256; k0 += 8){
        float4 av = *(const float4*)&x[((size_t)(b*256 + k0 + a_c))*NN + tl0 + a_t];
        *(float4*)&As[a_c][a_t] = av;
        float4 bv = *(const float4*)&W[(or0 + b_o)*256 + k0 + b_c];
        Bs[b_c+0][b_o] = bv.x; Bs[b_c+1][b_o] = bv.y;
        Bs[b_c+2][b_o] = bv.z; Bs[b_c+3][b_o] = bv.w;
        __syncthreads();
#pragma unroll
        for (int kk = 0; kk < 8; kk++){
            float4 a0 = *(const float4*)&As[kk][ty*8];
            float4 a1 = *(const float4*)&As[kk][ty*8+4];
            u64 ad[8];
            ad[0]=dup2(a0.x); ad[1]=dup2(a0.y); ad[2]=dup2(a0.z); ad[3]=dup2(a0.w);
            ad[4]=dup2(a1.x); ad[5]=dup2(a1.y); ad[6]=dup2(a1.z); ad[7]=dup2(a1.w);
            ulonglong2 b01 = *(const ulonglong2*)&Bs[kk][tx*8];
            ulonglong2 b23 = *(const ulonglong2*)&Bs[kk][tx*8+4];
#pragma unroll
            for (int i = 0; i < 8; i++){
                fma2(acc[i][0], ad[i], b01.x);
                fma2(acc[i][1], ad[i], b01.y);
                fma2(acc[i][2], ad[i], b23.x);
                fma2(acc[i][3], ad[i], b23.y);
            }
        }
        __syncthreads();
    }
    int trow  = t0 + ty*8;
    int obase = or0 + tx*8;
#pragma unroll
    for (int i = 0; i < 8; i++){
        float2 p0 = unpk(acc[i][0]), p1 = unpk(acc[i][1]);
        float2 p2 = unpk(acc[i][2]), p3 = unpk(acc[i][3]);
        float4 v0 = make_float4(p0.x, p0.y, p1.x, p1.y);
        float4 v1 = make_float4(p2.x, p2.y, p3.x, p3.y);
        *(float4*)&dst[(size_t)(trow + i)*256 + obase]     = v0;
        *(float4*)&dst[(size_t)(trow + i)*256 + obase + 4] = v1;
    }
}

/* ------------------------------------------------------------------ */
/* K2: key dash GEMM (64 tokens x 128 m, K=32), diag, global max       */
/* grid (144, 32), 256 thr                                             */
/* ------------------------------------------------------------------ */
__global__ void __launch_bounds__(256) k_kdash(const float* __restrict__ proj){
    __shared__ float projT[32][128];   /* scaled by NRM */
    __shared__ float kT[32][68];
    __shared__ float red[256];
    int bh = blockIdx.y, b = bh >> 3, h = bh & 7;
    int n0 = blockIdx.x * 64;
    int t  = threadIdx.x;

    for (int i = t; i < 1024; i += 256){
        float4 v = ((const float4*)proj)[i];
        int m = i >> 3, kq = (i & 7)*4;
        projT[kq+0][m] = v.x*NRM; projT[kq+1][m] = v.y*NRM;
        projT[kq+2][m] = v.z*NRM; projT[kq+3][m] = v.w*NRM;
    }
#pragma unroll
    for (int r = 0; r < 2; r++){
        int lin = r*256 + t;
        int tok = lin >> 3, kq = (lin & 7)*4;
        float4 v = *(const float4*)&g_k[((size_t)(b*NN + n0 + tok))*256 + h*32 + kq];
        kT[kq+0][tok] = v.x; kT[kq+1][tok] = v.y;
        kT[kq+2][tok] = v.z; kT[kq+3][tok] = v.w;
    }
    __syncthreads();

    int tx = t & 15, ty = t >> 4;   /* tx: 4-token group, ty: 8-m group */
    u64 acc[8][2];
#pragma unroll
    for (int i = 0; i < 8; i++){ acc[i][0] = 0ULL; acc[i][1] = 0ULL; }

#pragma unroll 4
    for (int kk = 0; kk < 32; kk++){
        ulonglong2 a2 = *(const ulonglong2*)&kT[kk][tx*4];
        float4 p0 = *(const float4*)&projT[kk][ty*8];
        float4 p1 = *(const float4*)&projT[kk][ty*8+4];
        u64 bd[8];
        bd[0]=dup2(p0.x); bd[1]=dup2(p0.y); bd[2]=dup2(p0.z); bd[3]=dup2(p0.w);
        bd[4]=dup2(p1.x); bd[5]=dup2(p1.y); bd[6]=dup2(p1.z); bd[7]=dup2(p1.w);
#pragma unroll
        for (int mi = 0; mi < 8; mi++){
            fma2(acc[mi][0], bd[mi], a2.x);
            fma2(acc[mi][1], bd[mi], a2.y);
        }
    }

    /* diag for 64 tokens */
    if (t < 64){
        float sq = 0.f;
#pragma unroll
        for (int kk = 0; kk < 32; kk++){ float v = kT[kk][t]; sq += v*v; }
        g_kdiag[bh*NN + n0 + t] = HALF_NRM2 * sq;
    }

    /* store dash + block max */
    float mx = -1e30f;
#pragma unroll
    for (int mi = 0; mi < 8; mi++){
        float2 q0 = unpk(acc[mi][0]), q1 = unpk(acc[mi][1]);
        mx = fmaxf(mx, fmaxf(fmaxf(q0.x,q0.y), fmaxf(q1.x,q1.y)));
        float4 v = make_float4(q0.x, q0.y, q1.x, q1.y);
        *(float4*)&g_kdashT[((size_t)bh*MF + ty*8 + mi)*NN + n0 + tx*4] = v;
    }
    red[t] = mx;
    __syncthreads();
    for (int s = 128; s > 0; s >>= 1){
        if (t < (unsigned)s) red[t] = fmaxf(red[t], red[t + s]);
        __syncthreads();
    }
    if (t == 0) atomicMaxF(&g_kmax[bh], red[0]);
}

/* ------------------------------------------------------------------ */
/* K3: ctx = kp^T @ [v | 1]  (f32x2 accumulation)                      */
/* ------------------------------------------------------------------ */
#define CTX_SPLITS 16
#define CTX_TILES  9
__global__ void __launch_bounds__(256) k_ctx(){
    __shared__ float kps[128][65];
    __shared__ float vs[64][36];
    int bh = blockIdx.y;
    int sp = blockIdx.x;
    int b = bh >> 3, h = bh & 7;
    int tid = threadIdx.x;
    int js = (tid >> 5) & 1;
    int m  = ((tid >> 6) << 5) | (tid & 31);
    int jbase = js * 16;
    float mk = g_kmax[bh];

    u64 acc2[8];
#pragma unroll
    for (int i = 0; i < 8; i++) acc2[i] = 0ULL;
    float accs = 0.f;

    for (int it = 0; it < CTX_TILES; it++){
        int n0 = sp*(CTX_TILES*64) + it*64;
#pragma unroll
        for (int i = 0; i < 32; i++){
            int lin = i*256 + tid;
            int mm = lin >> 6, nn = lin & 63;
            float d  = g_kdashT[((size_t)bh*MF + mm)*NN + n0 + nn];
            float dg = g_kdiag[bh*NN + n0 + nn];
            kps[mm][nn] = RATIO * (__expf(d - dg - mk) + EPSF);
        }
#pragma unroll
        for (int i = 0; i < 8; i++){
            int lin = i*256 + tid;
            int nn = lin >> 5, jj = lin & 31;
            vs[nn][jj] = g_v[((size_t)b*NN + n0 + nn)*256 + h*32 + jj];
        }
        if (tid < 64) vs[tid][32] = 1.0f;
        __syncthreads();

        for (int n = 0; n < 64; n++){
            float kp = kps[m][n];
            u64 kd = dup2(kp);
#pragma unroll
            for (int q = 0; q < 4; q++){
                ulonglong2 v2 = *(const ulonglong2*)&vs[n][jbase + q*4];
                fma2(acc2[q*2+0], kd, v2.x);
                fma2(acc2[q*2+1], kd, v2.y);
            }
            if (js == 0) accs += kp * vs[n][32];
        }
        __syncthreads();
    }
    size_t cb = ((size_t)bh*MF + m)*33;
#pragma unroll
    for (int q = 0; q < 8; q++){
        float2 p = unpk(acc2[q]);
        atomicAdd(&g_ctx[cb + jbase + q*2],     p.x);
        atomicAdd(&g_ctx[cb + jbase + q*2 + 1], p.y);
    }
    if (js == 0) atomicAdd(&g_ctx[cb + 32], accs);
}

/* ------------------------------------------------------------------ */
/* K4: fused q-features + qp@ctx + d_inv.  64 tokens per block.        */
/* dynamic smem layout (floats):                                       */
/*   [0..4096)      projT 32x128   (phase1)                            */
/*   [4096..6272)   qT    32x68    (phase1)                            */
/*   [0..8192)      qps   128x64   (phase2, overlays projT/qT)         */
/*   [8192..13312)  ctxs  128x40   (phase2; overlaid by outs 64x32)    */
/*   [13312..14336) pm    16x64                                        */
/*   [14336..14400) rowmax[64]; [14400..14464) diag[64]; [14464..) den */
/* ------------------------------------------------------------------ */
#define QA_SMEM_FLOATS 14528
#define S_PROJT 0
#define S_QT    4096
#define S_QPS   0
#define S_CTX   8192
#define S_OUTS  8192
#define S_PM    13312
#define S_RMAX  14336
#define S_DIAG  14400
#define S_DEN   14464

__global__ void __launch_bounds__(256) k_qattn(const float* __restrict__ proj){
    extern __shared__ float dyn[];
    int bh = blockIdx.y, b = bh >> 3, h = bh & 7;
    int n0 = blockIdx.x * 64;
    int t  = threadIdx.x;

    /* load projT (x NRM), qT, ctxs */
    for (int i = t; i < 1024; i += 256){
        float4 v = ((const float4*)proj)[i];
        int m = i >> 3, kq = (i & 7)*4;
        dyn[S_PROJT + (kq+0)*128 + m] = v.x*NRM;
        dyn[S_PROJT + (kq+1)*128 + m] = v.y*NRM;
        dyn[S_PROJT + (kq+2)*128 + m] = v.z*NRM;
        dyn[S_PROJT + (kq+3)*128 + m] = v.w*NRM;
    }
#pragma unroll
    for (int r = 0; r < 2; r++){
        int lin = r*256 + t;
        int tok = lin >> 3, kq = (lin & 7)*4;
        float4 v = *(const float4*)&g_q[((size_t)(b*NN + n0 + tok))*256 + h*32 + kq];
        dyn[S_QT + (kq+0)*68 + tok] = v.x;
        dyn[S_QT + (kq+1)*68 + tok] = v.y;
        dyn[S_QT + (kq+2)*68 + tok] = v.z;
        dyn[S_QT + (kq+3)*68 + tok] = v.w;
    }
    for (int i = t; i < 5120; i += 256){
        int m = i / 40, j = i % 40;
        dyn[S_CTX + i] = (j < 33) ? g_ctx[((size_t)bh*MF + m)*33 + j] : 0.f;
    }
    __syncthreads();

    /* GEMM1: dash[m][tok] in regs */
    int tx = t & 15, ty = t >> 4;
    u64 acc[8][2];
#pragma unroll
    for (int i = 0; i < 8; i++){ acc[i][0] = 0ULL; acc[i][1] = 0ULL; }
#pragma unroll 4
    for (int kk = 0; kk < 32; kk++){
        ulonglong2 a2 = *(const ulonglong2*)&dyn[S_QT + kk*68 + tx*4];
        float4 p0 = *(const float4*)&dyn[S_PROJT + kk*128 + ty*8];
        float4 p1 = *(const float4*)&dyn[S_PROJT + kk*128 + ty*8 + 4];
        u64 bd[8];
        bd[0]=dup2(p0.x); bd[1]=dup2(p0.y); bd[2]=dup2(p0.z); bd[3]=dup2(p0.w);
        bd[4]=dup2(p1.x); bd[5]=dup2(p1.y); bd[6]=dup2(p1.z); bd[7]=dup2(p1.w);
#pragma unroll
        for (int mi = 0; mi < 8; mi++){
            fma2(acc[mi][0], bd[mi], a2.x);
            fma2(acc[mi][1], bd[mi], a2.y);
        }
    }

    /* diag per token (reads qT before it is overwritten) */
    if (t < 64){
        float sq = 0.f;
#pragma unroll
        for (int kk = 0; kk < 32; kk++){ float v = dyn[S_QT + kk*68 + t]; sq += v*v; }
        dyn[S_DIAG + t] = HALF_NRM2 * sq;
    }

    /* partial row max over this thread's 8 m, per token */
    {
        float m0=-1e30f, m1=-1e30f, m2=-1e30f, m3=-1e30f;
#pragma unroll
        for (int mi = 0; mi < 8; mi++){
            float2 q0 = unpk(acc[mi][0]), q1 = unpk(acc[mi][1]);
            m0 = fmaxf(m0, q0.x); m1 = fmaxf(m1, q0.y);
            m2 = fmaxf(m2, q1.x); m3 = fmaxf(m3, q1.y);
        }
        dyn[S_PM + ty*64 + tx*4 + 0] = m0;
        dyn[S_PM + ty*64 + tx*4 + 1] = m1;
        dyn[S_PM + ty*64 + tx*4 + 2] = m2;
        dyn[S_PM + ty*64 + tx*4 + 3] = m3;
    }
    __syncthreads();
    if (t < 64){
        float mx = -1e30f;
#pragma unroll
        for (int i = 0; i < 16; i++) mx = fmaxf(mx, dyn[S_PM + i*64 + t]);
        dyn[S_RMAX + t] = mx;
    }
    __syncthreads();

    /* qps = RATIO*(exp(dash - diag - rowmax) + EPS), overlays projT/qT */
    {
        int tokb = tx*4;
        float d0 = dyn[S_DIAG + tokb+0] + dyn[S_RMAX + tokb+0];
        float d1 = dyn[S_DIAG + tokb+1] + dyn[S_RMAX + tokb+1];
        float d2 = dyn[S_DIAG + tokb+2] + dyn[S_RMAX + tokb+2];
        float d3 = dyn[S_DIAG + tokb+3] + dyn[S_RMAX + tokb+3];
#pragma unroll
        for (int mi = 0; mi < 8; mi++){
            float2 q0 = unpk(acc[mi][0]), q1 = unpk(acc[mi][1]);
            float4 v;
            v.x = RATIO * (__expf(q0.x - d0) + EPSF);
            v.y = RATIO * (__expf(q0.y - d1) + EPSF);
            v.z = RATIO * (__expf(q1.x - d2) + EPSF);
            v.w = RATIO * (__expf(q1.y - d3) + EPSF);
            *(float4*)&dyn[S_QPS + (ty*8 + mi)*64 + tokb] = v;
        }
    }
    __syncthreads();

    /* GEMM2: out[tok][j] = sum_m qps[m][tok]*ctx[m][j]   (j pairs, f32x2) */
    int w = t >> 5, l = t & 31;
    int tok = (w & 1)*32 + l;
    int jp0 = (w >> 1) * 5;           /* 5 j-pairs per warp group */
    u64 oacc[5];
#pragma unroll
    for (int p = 0; p < 5; p++) oacc[p] = 0ULL;
#pragma unroll 4
    for (int m = 0; m < 128; m++){
        u64 qd = dup2(dyn[S_QPS + m*64 + tok]);
        const u64* crow = (const u64*)&dyn[S_CTX + m*40 + jp0*2];
#pragma unroll
        for (int p = 0; p < 5; p++) fma2(oacc[p], qd, crow[p]);
    }
    /* denominator lives at j=32 -> pair index 16 -> group 3, p=1, lo */
    if ((w >> 1) == 3) dyn[S_DEN + tok] = unpk(oacc[1]).x;
    __syncthreads();
    {
        float inv = 1.0f / dyn[S_DEN + tok];
#pragma unroll
        for (int p = 0; p < 5; p++){
            int j = (jp0 + p)*2;
            if (j < 32){
                float2 o = unpk(oacc[p]);
                dyn[S_OUTS + tok*32 + j]     = o.x * inv;
                dyn[S_OUTS + tok*32 + j + 1] = o.y * inv;
            }
        }
    }
    __syncthreads();
    /* stream outs -> g_attn (coalesced) */
#pragma unroll
    for (int r = 0; r < 2; r++){
        int lin = r*256 + t;
        int tok2 = lin >> 3, j4 = (lin & 7)*4;
        float4 v = *(const float4*)&dyn[S_OUTS + tok2*32 + j4];
        *(float4*)&g_attn[((size_t)(b*NN + n0 + tok2))*256 + h*32 + j4] = v;
    }
}

/* ------------------------------------------------------------------ */
/* K5: final GEMM (f32x2), transposed store                            */
/* ------------------------------------------------------------------ */
__global__ void __launch_bounds__(256) k_final(float* __restrict__ out){
    __shared__ float As[8][128];
    __shared__ float Bs[8][128];
    int tid = threadIdx.x;
    int t0  = blockIdx.x * 128;
    int b   = t0 / NN;
    int tl0 = t0 % NN;
    int o0  = blockIdx.y * 128;

    int at = tid >> 1, ac = (tid & 1) * 4;
    int bo_ = tid >> 1, bc = (tid & 1) * 4;
    int tx = tid & 15, ty = tid >> 4;

    u64 acc[8][4];
#pragma unroll
    for (int i = 0; i < 8; i++)
#pragma unroll
        for (int j = 0; j < 4; j++) acc[i][j] = 0ULL;

    for (int k0 = 0; k0 < 256; k0 += 8){
        float4 av = *(const float4*)&g_attn[(size_t)(t0 + at)*256 + k0 + ac];
        As[ac+0][at] = av.x; As[ac+1][at] = av.y;
        As[ac+2][at] = av.z; As[ac+3][at] = av.w;
        float4 bv = *(const float4*)&g_Wc[(o0 + bo_)*256 + k0 + bc];
        Bs[bc+0][bo_] = bv.x; Bs[bc+1][bo_] = bv.y;
        Bs[bc+2][bo_] = bv.z; Bs[bc+3][bo_] = bv.w;
        __syncthreads();
#pragma unroll
        for (int kk = 0; kk < 8; kk++){
            float4 a0 = *(const float4*)&As[kk][ty*8];
            float4 a1 = *(const float4*)&As[kk][ty*8+4];
            u64 ad[8];
            ad[0]=dup2(a0.x); ad[1]=dup2(a0.y); ad[2]=dup2(a0.z); ad[3]=dup2(a0.w);
            ad[4]=dup2(a1.x); ad[5]=dup2(a1.y); ad[6]=dup2(a1.z); ad[7]=dup2(a1.w);
            ulonglong2 b01 = *(const ulonglong2*)&Bs[kk][tx*8];
            ulonglong2 b23 = *(const ulonglong2*)&Bs[kk][tx*8+4];
#pragma unroll
            for (int i = 0; i < 8; i++){
                fma2(acc[i][0], ad[i], b01.x);
                fma2(acc[i][1], ad[i], b01.y);
                fma2(acc[i][2], ad[i], b23.x);
                fma2(acc[i][3], ad[i], b23.y);
            }
        }
        __syncthreads();
    }
    /* acc[i][jc] : row = token t0+ty*8+i, cols o0+tx*8+2jc..+1 */
#pragma unroll
    for (int jc = 0; jc < 4; jc++){
#pragma unroll
        for (int half = 0; half < 2; half++){
            int o = o0 + tx*8 + jc*2 + half;
            float bias = g_bc[o];
            float vals[8];
#pragma unroll
            for (int i = 0; i < 8; i++){
                float2 p = unpk(acc[i][jc]);
                vals[i] = (half ? p.y : p.x) + bias;
            }
            size_t base = ((size_t)b*256 + o)*NN + tl0 + ty*8;
            *(float4*)&out[base]     = make_float4(vals[0], vals[1], vals[2], vals[3]);
            *(float4*)&out[base + 4] = make_float4(vals[4], vals[5], vals[6], vals[7]);
        }
    }
}

/* ------------------------------------------------------------------ */
extern "C" void kernel_launch(void* const* d_in, const int* in_sizes, int n_in,
                              void* d_out, int out_size){
    const float* x    = (const float*)d_in[0];
    const float* wq   = (const float*)d_in[1];
    const float* wk   = (const float*)d_in[2];
    const float* wv   = (const float*)d_in[3];
    const float* wo   = (const float*)d_in[4];
    const float* bo   = (const float*)d_in[5];
    const float* proj = (const float*)d_in[6];
    const float* wp   = (const float*)d_in[7];
    const float* bp   = (const float*)d_in[8];
    float* out = (float*)d_out;

    size_t qa_bytes = (size_t)QA_SMEM_FLOATS * sizeof(float);
    cudaFuncSetAttribute(k_qattn, cudaFuncAttributeMaxDynamicSharedMemorySize,
                         (int)qa_bytes);

    k_prep<<<256, 256>>>(wo, bo, wp, bp);
    k_init<<<(32*MF*33 + 255)/256, 256>>>();
    k_qkv<<<dim3(TT/128, 6), 256>>>(x, wq, wk, wv);
    k_kdash<<<dim3(NN/64, 32), 256>>>(proj);
    k_ctx<<<dim3(CTX_SPLITS, 32), 256>>>();
    k_qattn<<<dim3(NN/64, 32), 256, qa_bytes>>>(proj);
    k_final<<<dim3(TT/128, 2), 256>>>(out);
}

// round 4
// speedup vs baseline: 1.4775x; 1.3172x over previous
#include <cuda_runtime.h>
#include <cuda_fp16.h>
#include <math.h>

#define BB 4
#define CC 256
#define NHEAD 8
#define DHEAD 32
#define MF 128
#define NN 9216
#define TT (BB*NN)   /* 36864 */

#define NRM       0.4204482076268573f     /* 32^-0.25 */
#define HALF_NRM2 0.08838834764831845f    /* 0.5 * 32^-0.5 */
#define RATIO     0.08838834764831845f    /* 128^-0.5 */
#define EPSF      1e-4f

typedef unsigned long long u64;
typedef unsigned int u32;

/* ---------------- f32x2 (FFMA2) helpers ---------------- */
__device__ __forceinline__ u64 dup2(float v){
    u64 r; asm("mov.b64 %0, {%1,%1};" : "=l"(r) : "f"(v)); return r;
}
__device__ __forceinline__ void fma2(u64 &c, u64 a, u64 b){
    asm("fma.rn.f32x2 %0, %1, %2, %0;" : "+l"(c) : "l"(a), "l"(b));
}
__device__ __forceinline__ float2 unpk(u64 v){
    float2 r; asm("mov.b64 {%0,%1}, %2;" : "=f"(r.x), "=f"(r.y) : "l"(v)); return r;
}

/* ---------------- mma.sync helpers (base-target tensor core) -------- */
__device__ __forceinline__ u32 smem_u32(const void* p){
    u32 a; asm("{ .reg .u64 t; cvta.to.shared.u64 t, %1; cvt.u32.u64 %0, t; }"
               : "=r"(a) : "l"(p)); return a;
}
#define LDM4(r, a) \
    asm volatile("ldmatrix.sync.aligned.m8n8.x4.shared.b16 {%0,%1,%2,%3}, [%4];" \
        : "=r"((r)[0]),"=r"((r)[1]),"=r"((r)[2]),"=r"((r)[3]) : "r"(a))
#define MMA16816(c, a, b0, b1) \
    asm volatile("mma.sync.aligned.m16n8k16.row.col.f32.f16.f16.f32 " \
        "{%0,%1,%2,%3}, {%4,%5,%6,%7}, {%8,%9}, {%0,%1,%2,%3};" \
        : "+f"((c)[0]),"+f"((c)[1]),"+f"((c)[2]),"+f"((c)[3]) \
        : "r"((a)[0]),"r"((a)[1]),"r"((a)[2]),"r"((a)[3]), "r"(b0),"r"(b1))

/* split a,b into fp16 hi pair + fp16 residual pair (packed u32) */
__device__ __forceinline__ void f16split2(float a, float b, u32 &h, u32 &l){
    __half2 hh = __floats2half2_rn(a, b);
    float2 bk = __half22float2(hh);
    __half2 ll = __floats2half2_rn(a - bk.x, b - bk.y);
    h = *(u32*)&hh; l = *(u32*)&ll;
}

/* smem tile layout for mma GEMMs: 128 rows x 64 halves, pitch 144 B */
#define PITCHB 144
#define SA_H 0
#define SA_L 18432
#define SB_H 36864
#define SB_L 55296
#define G2_SMEM 73728

/* ---------------- scratch ---------------- */
__device__ float g_q[(size_t)TT*CC];
__device__ float g_k[(size_t)TT*CC];
__device__ float g_v[(size_t)TT*CC];
__device__ float g_attn[(size_t)TT*CC];
__device__ float g_kdashT[(size_t)32*MF*NN];   /* [bh][m][n] */
__device__ float g_kdiag[32*NN];
__device__ float g_kmax[32];
__device__ float g_ctx[32*MF*33];              /* [bh][m][j], j=32 is k_sum */
__device__ float g_Wc[CC*CC];
__device__ float g_bc[CC];

__device__ __forceinline__ void atomicMaxF(float* a, float v){
    int old = __float_as_int(*a);
    while (__int_as_float(old) < v){
        int cur = atomicCAS((int*)a, old, __float_as_int(v));
        if (cur == old) break;
        old = cur;
    }
}

/* ------------------------------------------------------------------ */
/* K0: fold wo + 1x1 conv into one weight                              */
/* ------------------------------------------------------------------ */
__global__ void k_prep(const float* __restrict__ wo, const float* __restrict__ bo,
                       const float* __restrict__ wp, const float* __restrict__ bp){
    int o2 = blockIdx.x;
    int c  = threadIdx.x;
    float s = 0.f;
    for (int o = 0; o < 256; o++) s += wp[o2*256 + o] * wo[o*256 + c];
    g_Wc[o2*256 + c] = s;
    if (c == 0){
        float sb = 0.f;
        for (int o = 0; o < 256; o++) sb += wp[o2*256 + o] * bo[o];
        g_bc[o2] = sb + bp[o2];
    }
}

__global__ void k_init(){
    int i = blockIdx.x*blockDim.x + threadIdx.x;
    if (i < 32*MF*33) g_ctx[i] = 0.f;
    if (i < 32) g_kmax[i] = -1e30f;
}

/* ------------------------------------------------------------------ */
/* mma micro-kernel body shared by K1/K5: operates on smem tiles.      */
/* 8 warps, warp (wm,wn) owns 64x32. 4 k-steps of 16 per chunk.        */
/* ------------------------------------------------------------------ */
__device__ __forceinline__ void mma_chunk(u32 smb, int wm, int wn, int lane,
                                          float c[4][4][4]){
    u32 a_off = (u32)((wm + (lane & 15))*PITCHB + (lane >> 4)*16);
    u32 b_off = (u32)((wn + (lane & 7) + ((lane >> 4) & 1)*8)*PITCHB
                      + ((lane >> 3) & 1)*16);
#pragma unroll
    for (int ks = 0; ks < 4; ks++){
        u32 ah[4][4], bh[2][4];
#pragma unroll
        for (int mt = 0; mt < 4; mt++)
            LDM4(ah[mt], smb + SA_H + a_off + mt*(16*PITCHB) + ks*32);
#pragma unroll
        for (int np = 0; np < 2; np++)
            LDM4(bh[np], smb + SB_H + b_off + np*(16*PITCHB) + ks*32);
#pragma unroll
        for (int mt = 0; mt < 4; mt++)
#pragma unroll
            for (int nt = 0; nt < 4; nt++)
                MMA16816(c[mt][nt], ah[mt], bh[nt>>1][(nt&1)*2], bh[nt>>1][(nt&1)*2+1]);
        {
            u32 bl[2][4];
#pragma unroll
            for (int np = 0; np < 2; np++)
                LDM4(bl[np], smb + SB_L + b_off + np*(16*PITCHB) + ks*32);
#pragma unroll
            for (int mt = 0; mt < 4; mt++)
#pragma unroll
                for (int nt = 0; nt < 4; nt++)
                    MMA16816(c[mt][nt], ah[mt], bl[nt>>1][(nt&1)*2], bl[nt>>1][(nt&1)*2+1]);
        }
        {
            u32 al[4][4];
#pragma unroll
            for (int mt = 0; mt < 4; mt++)
                LDM4(al[mt], smb + SA_L + a_off + mt*(16*PITCHB) + ks*32);
#pragma unroll
            for (int mt = 0; mt < 4; mt++)
#pragma unroll
                for (int nt = 0; nt < 4; nt++)
                    MMA16816(c[mt][nt], al[mt], bh[nt>>1][(nt&1)*2], bh[nt>>1][(nt&1)*2+1]);
        }
    }
}

/* ------------------------------------------------------------------ */
/* K1: QKV GEMM via mma.sync fp16-split.                               */
/* grid (288, 6), 256 thr. Tile 128 tok x 128 out, K=256 (4x64).       */
/* ------------------------------------------------------------------ */
__global__ void __launch_bounds__(256, 2) k_qkv_t(const float* __restrict__ x,
        const float* __restrict__ wq, const float* __restrict__ wk,
        const float* __restrict__ wv){
    extern __shared__ char sm[];
    u32 smb = smem_u32(sm);
    int tid = threadIdx.x, wid = tid >> 5, lane = tid & 31;
    int t0 = blockIdx.x * 128;
    int b = t0 / NN, tl0 = t0 % NN;
    int oc = blockIdx.y;
    const float* W = (oc < 2) ? wq : (oc < 4 ? wk : wv);
    float* dst     = (oc < 2) ? g_q : (oc < 4 ? g_k : g_v);
    int or0 = (oc & 1) * 128;

    int wm = (wid >> 2) * 64, wn = (wid & 3) * 32;
    int tq  = lane * 4;              /* token group for A loads */
    int cg2 = wid * 2;               /* column pair for A loads */
    int rb  = tid >> 4, cf = (tid & 15) * 4;   /* B loads */

    float c[4][4][4];
#pragma unroll
    for (int mt = 0; mt < 4; mt++)
#pragma unroll
        for (int nt = 0; nt < 4; nt++)
#pragma unroll
            for (int r = 0; r < 4; r++) c[mt][nt][r] = 0.f;

    for (int ch = 0; ch < 4; ch++){
        int c0 = ch * 64;
        /* A: x is c-major; load float4 over tokens for col pair (c, c+1) */
#pragma unroll
        for (int u = 0; u < 4; u++){
            int cl = u*16 + cg2;
            const float* p = &x[((size_t)(b*256 + c0 + cl))*NN + tl0 + tq];
            float4 f0 = *(const float4*)p;
            float4 f1 = *(const float4*)(p + NN);
            const float* e0 = (const float*)&f0;
            const float* e1 = (const float*)&f1;
#pragma unroll
            for (int j = 0; j < 4; j++){
                u32 h, l;
                f16split2(e0[j], e1[j], h, l);
                u32 off = (u32)((tq + j)*PITCHB + cl*2);
                *(u32*)(sm + SA_H + off) = h;
                *(u32*)(sm + SA_L + off) = l;
            }
        }
        /* B: weights row-major */
#pragma unroll
        for (int s = 0; s < 8; s++){
            int row = rb + s*16;
            float4 f = *(const float4*)&W[(size_t)(or0 + row)*256 + c0 + cf];
            u32 h0, l0, h1, l1;
            f16split2(f.x, f.y, h0, l0);
            f16split2(f.z, f.w, h1, l1);
            u32 off = (u32)(row*PITCHB + cf*2);
            *(uint2*)(sm + SB_H + off) = make_uint2(h0, h1);
            *(uint2*)(sm + SB_L + off) = make_uint2(l0, l1);
        }
        __syncthreads();
        mma_chunk(smb, wm, wn, lane, c);
        __syncthreads();
    }

    /* direct store: row-major dst[t][out] */
#pragma unroll
    for (int mt = 0; mt < 4; mt++){
#pragma unroll
        for (int nt = 0; nt < 4; nt++){
            int row = t0 + wm + mt*16 + (lane >> 2);
            int col = or0 + wn + nt*8 + (lane & 3)*2;
            *(float2*)&dst[(size_t)row*256 + col] =
                make_float2(c[mt][nt][0], c[mt][nt][1]);
            *(float2*)&dst[(size_t)(row+8)*256 + col] =
                make_float2(c[mt][nt][2], c[mt][nt][3]);
        }
    }
}

/* ------------------------------------------------------------------ */
/* K5: final GEMM via mma.sync fp16-split; transposed store + bias.    */
/* grid (288, 2), 256 thr. out[b][o][n].                               */
/* ------------------------------------------------------------------ */
__global__ void __launch_bounds__(256, 2) k_final_t(float* __restrict__ out){
    extern __shared__ char sm[];
    u32 smb = smem_u32(sm);
    int tid = threadIdx.x, wid = tid >> 5, lane = tid & 31;
    int t0 = blockIdx.x * 128;
    int b = t0 / NN, tl0 = t0 % NN;
    int o0 = blockIdx.y * 128;

    int wm = (wid >> 2) * 64, wn = (wid & 3) * 32;
    int rb = tid >> 4, cf = (tid & 15) * 4;

    float c[4][4][4];
#pragma unroll
    for (int mt = 0; mt < 4; mt++)
#pragma unroll
        for (int nt = 0; nt < 4; nt++)
#pragma unroll
            for (int r = 0; r < 4; r++) c[mt][nt][r] = 0.f;

    for (int ch = 0; ch < 4; ch++){
        int c0 = ch * 64;
#pragma unroll
        for (int s = 0; s < 8; s++){
            int row = rb + s*16;
            float4 fa = *(const float4*)&g_attn[(size_t)(t0 + row)*256 + c0 + cf];
            float4 fb = *(const float4*)&g_Wc[(size_t)(o0 + row)*256 + c0 + cf];
            u32 h0, l0, h1, l1;
            u32 off = (u32)(row*PITCHB + cf*2);
            f16split2(fa.x, fa.y, h0, l0);
            f16split2(fa.z, fa.w, h1, l1);
            *(uint2*)(sm + SA_H + off) = make_uint2(h0, h1);
            *(uint2*)(sm + SA_L + off) = make_uint2(l0, l1);
            f16split2(fb.x, fb.y, h0, l0);
            f16split2(fb.z, fb.w, h1, l1);
            *(uint2*)(sm + SB_H + off) = make_uint2(h0, h1);
            *(uint2*)(sm + SB_L + off) = make_uint2(l0, l1);
        }
        __syncthreads();
        mma_chunk(smb, wm, wn, lane, c);
        __syncthreads();
    }

    /* stage transposed [o_local][tok_local] then coalesced tokens */
    float* stage = (float*)sm;     /* 128 x 132 floats = 67584 B */
#pragma unroll
    for (int mt = 0; mt < 4; mt++){
#pragma unroll
        for (int nt = 0; nt < 4; nt++){
            int r = wm + mt*16 + (lane >> 2);
            int cc = wn + nt*8 + (lane & 3)*2;
            stage[cc*132 + r]         = c[mt][nt][0];
            stage[(cc+1)*132 + r]     = c[mt][nt][1];
            stage[cc*132 + r + 8]     = c[mt][nt][2];
            stage[(cc+1)*132 + r + 8] = c[mt][nt][3];
        }
    }
    __syncthreads();
#pragma unroll
    for (int i2 = 0; i2 < 16; i2++){
        int idx = i2*256 + tid;
        int cc = idx >> 5, t4 = (idx & 31) * 4;
        int o = o0 + cc;
        float bias = g_bc[o];
        float4 v = *(float4*)&stage[cc*132 + t4];
        v.x += bias; v.y += bias; v.z += bias; v.w += bias;
        *(float4*)&out[((size_t)b*256 + o)*NN + tl0 + t4] = v;
    }
}

/* ------------------------------------------------------------------ */
/* K2: key dash GEMM (64 tokens x 128 m, K=32), diag, global max       */
/* ------------------------------------------------------------------ */
__global__ void __launch_bounds__(256) k_kdash(const float* __restrict__ proj){
    __shared__ float projT[32][128];
    __shared__ float kT[32][68];
    __shared__ float red[256];
    int bh = blockIdx.y, b = bh >> 3, h = bh & 7;
    int n0 = blockIdx.x * 64;
    int t  = threadIdx.x;

    for (int i = t; i < 1024; i += 256){
        float4 v = ((const float4*)proj)[i];
        int m = i >> 3, kq = (i & 7)*4;
        projT[kq+0][m] = v.x*NRM; projT[kq+1][m] = v.y*NRM;
        projT[kq+2][m] = v.z*NRM; projT[kq+3][m] = v.w*NRM;
    }
#pragma unroll
    for (int r = 0; r < 2; r++){
        int lin = r*256 + t;
        int tok = lin >> 3, kq = (lin & 7)*4;
        float4 v = *(const float4*)&g_k[((size_t)(b*NN + n0 + tok))*256 + h*32 + kq];
        kT[kq+0][tok] = v.x; kT[kq+1][tok] = v.y;
        kT[kq+2][tok] = v.z; kT[kq+3][tok] = v.w;
    }
    __syncthreads();

    int tx = t & 15, ty = t >> 4;
    u64 acc[8][2];
#pragma unroll
    for (int i = 0; i < 8; i++){ acc[i][0] = 0ULL; acc[i][1] = 0ULL; }

#pragma unroll 4
    for (int kk = 0; kk < 32; kk++){
        ulonglong2 a2 = *(const ulonglong2*)&kT[kk][tx*4];
        float4 p0 = *(const float4*)&projT[kk][ty*8];
        float4 p1 = *(const float4*)&projT[kk][ty*8+4];
        u64 bd[8];
        bd[0]=dup2(p0.x); bd[1]=dup2(p0.y); bd[2]=dup2(p0.z); bd[3]=dup2(p0.w);
        bd[4]=dup2(p1.x); bd[5]=dup2(p1.y); bd[6]=dup2(p1.z); bd[7]=dup2(p1.w);
#pragma unroll
        for (int mi = 0; mi < 8; mi++){
            fma2(acc[mi][0], bd[mi], a2.x);
            fma2(acc[mi][1], bd[mi], a2.y);
        }
    }

    if (t < 64){
        float sq = 0.f;
#pragma unroll
        for (int kk = 0; kk < 32; kk++){ float v = kT[kk][t]; sq += v*v; }
        g_kdiag[bh*NN + n0 + t] = HALF_NRM2 * sq;
    }

    float mx = -1e30f;
#pragma unroll
    for (int mi = 0; mi < 8; mi++){
        float2 q0 = unpk(acc[mi][0]), q1 = unpk(acc[mi][1]);
        mx = fmaxf(mx, fmaxf(fmaxf(q0.x,q0.y), fmaxf(q1.x,q1.y)));
        float4 v = make_float4(q0.x, q0.y, q1.x, q1.y);
        *(float4*)&g_kdashT[((size_t)bh*MF + ty*8 + mi)*NN + n0 + tx*4] = v;
    }
    red[t] = mx;
    __syncthreads();
    for (int s = 128; s > 0; s >>= 1){
        if (t < (unsigned)s) red[t] = fmaxf(red[t], red[t + s]);
        __syncthreads();
    }
    if (t == 0) atomicMaxF(&g_kmax[bh], red[0]);
}

/* ------------------------------------------------------------------ */
/* K3: ctx = kp^T @ [v | 1]                                            */
/* ------------------------------------------------------------------ */
#define CTX_SPLITS 16
#define CTX_TILES  9
__global__ void __launch_bounds__(256) k_ctx(){
    __shared__ float kps[128][65];
    __shared__ float vs[64][36];
    int bh = blockIdx.y;
    int sp = blockIdx.x;
    int b = bh >> 3, h = bh & 7;
    int tid = threadIdx.x;
    int js = (tid >> 5) & 1;
    int m  = ((tid >> 6) << 5) | (tid & 31);
    int jbase = js * 16;
    float mk = g_kmax[bh];

    u64 acc2[8];
#pragma unroll
    for (int i = 0; i < 8; i++) acc2[i] = 0ULL;
    float accs = 0.f;

    for (int it = 0; it < CTX_TILES; it++){
        int n0 = sp*(CTX_TILES*64) + it*64;
#pragma unroll
        for (int i = 0; i < 32; i++){
            int lin = i*256 + tid;
            int mm = lin >> 6, nn = lin & 63;
            float d  = g_kdashT[((size_t)bh*MF + mm)*NN + n0 + nn];
            float dg = g_kdiag[bh*NN + n0 + nn];
            kps[mm][nn] = RATIO * (__expf(d - dg - mk) + EPSF);
        }
#pragma unroll
        for (int i = 0; i < 8; i++){
            int lin = i*256 + tid;
            int nn = lin >> 5, jj = lin & 31;
            vs[nn][jj] = g_v[((size_t)b*NN + n0 + nn)*256 + h*32 + jj];
        }
        if (tid < 64) vs[tid][32] = 1.0f;
        __syncthreads();

        for (int n = 0; n < 64; n++){
            float kp = kps[m][n];
            u64 kd = dup2(kp);
#pragma unroll
            for (int q = 0; q < 4; q++){
                ulonglong2 v2 = *(const ulonglong2*)&vs[n][jbase + q*4];
                fma2(acc2[q*2+0], kd, v2.x);
                fma2(acc2[q*2+1], kd, v2.y);
            }
            if (js == 0) accs += kp * vs[n][32];
        }
        __syncthreads();
    }
    size_t cb = ((size_t)bh*MF + m)*33;
#pragma unroll
    for (int q = 0; q < 8; q++){
        float2 p = unpk(acc2[q]);
        atomicAdd(&g_ctx[cb + jbase + q*2],     p.x);
        atomicAdd(&g_ctx[cb + jbase + q*2 + 1], p.y);
    }
    if (js == 0) atomicAdd(&g_ctx[cb + 32], accs);
}

/* ------------------------------------------------------------------ */
/* K4: fused q-features + qp@ctx + d_inv.  64 tokens per block.        */
/* ------------------------------------------------------------------ */
#define QA_SMEM_FLOATS 14528
#define S_PROJT 0
#define S_QT    4096
#define S_QPS   0
#define S_CTX   8192
#define S_OUTS  8192
#define S_PM    13312
#define S_RMAX  14336
#define S_DIAG  14400
#define S_DEN   14464

__global__ void __launch_bounds__(256) k_qattn(const float* __restrict__ proj){
    extern __shared__ float dyn[];
    int bh = blockIdx.y, b = bh >> 3, h = bh & 7;
    int n0 = blockIdx.x * 64;
    int t  = threadIdx.x;

    for (int i = t; i < 1024; i += 256){
        float4 v = ((const float4*)proj)[i];
        int m = i >> 3, kq = (i & 7)*4;
        dyn[S_PROJT + (kq+0)*128 + m] = v.x*NRM;
        dyn[S_PROJT + (kq+1)*128 + m] = v.y*NRM;
        dyn[S_PROJT + (kq+2)*128 + m] = v.z*NRM;
        dyn[S_PROJT + (kq+3)*128 + m] = v.w*NRM;
    }
#pragma unroll
    for (int r = 0; r < 2; r++){
        int lin = r*256 + t;
        int tok = lin >> 3, kq = (lin & 7)*4;
        float4 v = *(const float4*)&g_q[((size_t)(b*NN + n0 + tok))*256 + h*32 + kq];
        dyn[S_QT + (kq+0)*68 + tok] = v.x;
        dyn[S_QT + (kq+1)*68 + tok] = v.y;
        dyn[S_QT + (kq+2)*68 + tok] = v.z;
        dyn[S_QT + (kq+3)*68 + tok] = v.w;
    }
    for (int i = t; i < 5120; i += 256){
        int m = i / 40, j = i % 40;
        dyn[S_CTX + i] = (j < 33) ? g_ctx[((size_t)bh*MF + m)*33 + j] : 0.f;
    }
    __syncthreads();

    int tx = t & 15, ty = t >> 4;
    u64 acc[8][2];
#pragma unroll
    for (int i = 0; i < 8; i++){ acc[i][0] = 0ULL; acc[i][1] = 0ULL; }
#pragma unroll 4
    for (int kk = 0; kk < 32; kk++){
        ulonglong2 a2 = *(const ulonglong2*)&dyn[S_QT + kk*68 + tx*4];
        float4 p0 = *(const float4*)&dyn[S_PROJT + kk*128 + ty*8];
        float4 p1 = *(const float4*)&dyn[S_PROJT + kk*128 + ty*8 + 4];
        u64 bd[8];
        bd[0]=dup2(p0.x); bd[1]=dup2(p0.y); bd[2]=dup2(p0.z); bd[3]=dup2(p0.w);
        bd[4]=dup2(p1.x); bd[5]=dup2(p1.y); bd[6]=dup2(p1.z); bd[7]=dup2(p1.w);
#pragma unroll
        for (int mi = 0; mi < 8; mi++){
            fma2(acc[mi][0], bd[mi], a2.x);
            fma2(acc[mi][1], bd[mi], a2.y);
        }
    }

    if (t < 64){
        float sq = 0.f;
#pragma unroll
        for (int kk = 0; kk < 32; kk++){ float v = dyn[S_QT + kk*68 + t]; sq += v*v; }
        dyn[S_DIAG + t] = HALF_NRM2 * sq;
    }

    {
        float m0=-1e30f, m1=-1e30f, m2=-1e30f, m3=-1e30f;
#pragma unroll
        for (int mi = 0; mi < 8; mi++){
            float2 q0 = unpk(acc[mi][0]), q1 = unpk(acc[mi][1]);
            m0 = fmaxf(m0, q0.x); m1 = fmaxf(m1, q0.y);
            m2 = fmaxf(m2, q1.x); m3 = fmaxf(m3, q1.y);
        }
        dyn[S_PM + ty*64 + tx*4 + 0] = m0;
        dyn[S_PM + ty*64 + tx*4 + 1] = m1;
        dyn[S_PM + ty*64 + tx*4 + 2] = m2;
        dyn[S_PM + ty*64 + tx*4 + 3] = m3;
    }
    __syncthreads();
    if (t < 64){
        float mx = -1e30f;
#pragma unroll
        for (int i = 0; i < 16; i++) mx = fmaxf(mx, dyn[S_PM + i*64 + t]);
        dyn[S_RMAX + t] = mx;
    }
    __syncthreads();

    {
        int tokb = tx*4;
        float d0 = dyn[S_DIAG + tokb+0] + dyn[S_RMAX + tokb+0];
        float d1 = dyn[S_DIAG + tokb+1] + dyn[S_RMAX + tokb+1];
        float d2 = dyn[S_DIAG + tokb+2] + dyn[S_RMAX + tokb+2];
        float d3 = dyn[S_DIAG + tokb+3] + dyn[S_RMAX + tokb+3];
#pragma unroll
        for (int mi = 0; mi < 8; mi++){
            float2 q0 = unpk(acc[mi][0]), q1 = unpk(acc[mi][1]);
            float4 v;
            v.x = RATIO * (__expf(q0.x - d0) + EPSF);
            v.y = RATIO * (__expf(q0.y - d1) + EPSF);
            v.z = RATIO * (__expf(q1.x - d2) + EPSF);
            v.w = RATIO * (__expf(q1.y - d3) + EPSF);
            *(float4*)&dyn[S_QPS + (ty*8 + mi)*64 + tokb] = v;
        }
    }
    __syncthreads();

    int w = t >> 5, l = t & 31;
    int tok = (w & 1)*32 + l;
    int jp0 = (w >> 1) * 5;
    u64 oacc[5];
#pragma unroll
    for (int p = 0; p < 5; p++) oacc[p] = 0ULL;
#pragma unroll 4
    for (int m = 0; m < 128; m++){
        u64 qd = dup2(dyn[S_QPS + m*64 + tok]);
        const u64* crow = (const u64*)&dyn[S_CTX + m*40 + jp0*2];
#pragma unroll
        for (int p = 0; p < 5; p++) fma2(oacc[p], qd, crow[p]);
    }
    if ((w >> 1) == 3) dyn[S_DEN + tok] = unpk(oacc[1]).x;
    __syncthreads();
    {
        float inv = 1.0f / dyn[S_DEN + tok];
#pragma unroll
        for (int p = 0; p < 5; p++){
            int j = (jp0 + p)*2;
            if (j < 32){
                float2 o = unpk(oacc[p]);
                dyn[S_OUTS + tok*32 + j]     = o.x * inv;
                dyn[S_OUTS + tok*32 + j + 1] = o.y * inv;
            }
        }
    }
    __syncthreads();
#pragma unroll
    for (int r = 0; r < 2; r++){
        int lin = r*256 + t;
        int tok2 = lin >> 3, j4 = (lin & 7)*4;
        float4 v = *(const float4*)&dyn[S_OUTS + tok2*32 + j4];
        *(float4*)&g_attn[((size_t)(b*NN + n0 + tok2))*256 + h*32 + j4] = v;
    }
}

/* ------------------------------------------------------------------ */
extern "C" void kernel_launch(void* const* d_in, const int* in_sizes, int n_in,
                              void* d_out, int out_size){
    const float* x    = (const float*)d_in[0];
    const float* wq   = (const float*)d_in[1];
    const float* wk   = (const float*)d_in[2];
    const float* wv   = (const float*)d_in[3];
    const float* wo   = (const float*)d_in[4];
    const float* bo   = (const float*)d_in[5];
    const float* proj = (const float*)d_in[6];
    const float* wp   = (const float*)d_in[7];
    const float* bp   = (const float*)d_in[8];
    float* out = (float*)d_out;

    size_t qa_bytes = (size_t)QA_SMEM_FLOATS * sizeof(float);
    cudaFuncSetAttribute(k_qattn, cudaFuncAttributeMaxDynamicSharedMemorySize,
                         (int)qa_bytes);
    cudaFuncSetAttribute(k_qkv_t, cudaFuncAttributeMaxDynamicSharedMemorySize, G2_SMEM);
    cudaFuncSetAttribute(k_final_t, cudaFuncAttributeMaxDynamicSharedMemorySize, G2_SMEM);

    k_prep<<<256, 256>>>(wo, bo, wp, bp);
    k_init<<<(32*MF*33 + 255)/256, 256>>>();
    k_qkv_t<<<dim3(TT/128, 6), 256, G2_SMEM>>>(x, wq, wk, wv);
    k_kdash<<<dim3(NN/64, 32), 256>>>(proj);
    k_ctx<<<dim3(CTX_SPLITS, 32), 256>>>();
    k_qattn<<<dim3(NN/64, 32), 256, qa_bytes>>>(proj);
    k_final_t<<<dim3(TT/128, 2), 256, G2_SMEM>>>(out);
}

// round 5
// speedup vs baseline: 1.5713x; 1.0635x over previous
#include <cuda_runtime.h>
#include <cuda_fp16.h>
#include <math.h>

#define BB 4
#define CC 256
#define NHEAD 8
#define DHEAD 32
#define MF 128
#define NN 9216
#define TT (BB*NN)   /* 36864 */

#define NRM       0.4204482076268573f     /* 32^-0.25 */
#define HALF_NRM2 0.08838834764831845f    /* 0.5 * 32^-0.5 */
#define RATIO     0.08838834764831845f    /* 128^-0.5 */
#define EPSF      1e-4f
#define KP_SCALE  64.0f
#define QP_SCALE  64.0f
#define KP_RATIO  (RATIO*KP_SCALE)
#define QP_RATIO  (RATIO*QP_SCALE)

typedef unsigned long long u64;
typedef unsigned int u32;

/* ---------------- mma.sync helpers ---------------- */
__device__ __forceinline__ u32 smem_u32(const void* p){
    u32 a; asm("{ .reg .u64 t; cvta.to.shared.u64 t, %1; cvt.u32.u64 %0, t; }"
               : "=r"(a) : "l"(p)); return a;
}
#define LDM4(r, a) \
    asm volatile("ldmatrix.sync.aligned.m8n8.x4.shared.b16 {%0,%1,%2,%3}, [%4];" \
        : "=r"((r)[0]),"=r"((r)[1]),"=r"((r)[2]),"=r"((r)[3]) : "r"(a))
#define LDM4T(r, a) \
    asm volatile("ldmatrix.sync.aligned.m8n8.x4.trans.shared.b16 {%0,%1,%2,%3}, [%4];" \
        : "=r"((r)[0]),"=r"((r)[1]),"=r"((r)[2]),"=r"((r)[3]) : "r"(a))
#define MMA16816(c, a, b0, b1) \
    asm volatile("mma.sync.aligned.m16n8k16.row.col.f32.f16.f16.f32 " \
        "{%0,%1,%2,%3}, {%4,%5,%6,%7}, {%8,%9}, {%0,%1,%2,%3};" \
        : "+f"((c)[0]),"+f"((c)[1]),"+f"((c)[2]),"+f"((c)[3]) \
        : "r"((a)[0]),"r"((a)[1]),"r"((a)[2]),"r"((a)[3]), "r"(b0),"r"(b1))

__device__ __forceinline__ void f16split2(float a, float b, u32 &h, u32 &l){
    __half2 hh = __floats2half2_rn(a, b);
    float2 bk = __half22float2(hh);
    __half2 ll = __floats2half2_rn(a - bk.x, b - bk.y);
    h = *(u32*)&hh; l = *(u32*)&ll;
}
__device__ __forceinline__ float2 h2f(u32 h, u32 l){
    float2 a = __half22float2(*(__half2*)&h);
    float2 b = __half22float2(*(__half2*)&l);
    return make_float2(a.x + b.x, a.y + b.y);
}

/* qkv/final GEMM smem: 128 rows x 64 halves, pitch 144 B */
#define PITCHB 144
#define SA_H 0
#define SA_L 18432
#define SB_H 36864
#define SB_L 55296
#define G2_SMEM 73728

/* ---------------- scratch ---------------- */
__device__ u32 g_qh[(size_t)TT*128];
__device__ u32 g_ql[(size_t)TT*128];
__device__ u32 g_kh[(size_t)TT*128];
__device__ u32 g_kl[(size_t)TT*128];
__device__ u32 g_vh[(size_t)TT*128];
__device__ u32 g_vl[(size_t)TT*128];
__device__ float g_attn[(size_t)TT*CC];
__device__ float g_kmax[32];
__device__ float g_ctx[32*MF*33];
__device__ float g_Wc[CC*CC];
__device__ float g_bc[CC];
__device__ u32 g_projh[2048];   /* [m=128][pair=16], NRM folded */
__device__ u32 g_projl[2048];

__device__ __forceinline__ void atomicMaxF(float* a, float v){
    int old = __float_as_int(*a);
    while (__int_as_float(old) < v){
        int cur = atomicCAS((int*)a, old, __float_as_int(v));
        if (cur == old) break;
        old = cur;
    }
}

/* ------------------------------------------------------------------ */
__global__ void k_prep(const float* __restrict__ wo, const float* __restrict__ bo,
                       const float* __restrict__ wp, const float* __restrict__ bp){
    int o2 = blockIdx.x;
    int c  = threadIdx.x;
    float s = 0.f;
    for (int o = 0; o < 256; o++) s += wp[o2*256 + o] * wo[o*256 + c];
    g_Wc[o2*256 + c] = s;
    if (c == 0){
        float sb = 0.f;
        for (int o = 0; o < 256; o++) sb += wp[o2*256 + o] * bo[o];
        g_bc[o2] = sb + bp[o2];
    }
}

__global__ void k_prep_proj(const float* __restrict__ proj){
    int i = blockIdx.x*256 + threadIdx.x;   /* 2048 */
    int m = i >> 4, p = i & 15;
    float a = proj[m*32 + p*2]     * NRM;
    float b = proj[m*32 + p*2 + 1] * NRM;
    u32 h, l;
    f16split2(a, b, h, l);
    g_projh[i] = h; g_projl[i] = l;
}

__global__ void k_init(){
    int i = blockIdx.x*blockDim.x + threadIdx.x;
    if (i < 32*MF*33) g_ctx[i] = 0.f;
    if (i < 32) g_kmax[i] = -1e30f;
}

/* ------------------------------------------------------------------ */
/* shared mma micro-body for qkv/final (from R4, unchanged)            */
/* ------------------------------------------------------------------ */
__device__ __forceinline__ void mma_chunk(u32 smb, int wm, int wn, int lane,
                                          float c[4][4][4]){
    u32 a_off = (u32)((wm + (lane & 15))*PITCHB + (lane >> 4)*16);
    u32 b_off = (u32)((wn + (lane & 7) + ((lane >> 4) & 1)*8)*PITCHB
                      + ((lane >> 3) & 1)*16);
#pragma unroll
    for (int ks = 0; ks < 4; ks++){
        u32 ah[4][4], bh[2][4];
#pragma unroll
        for (int mt = 0; mt < 4; mt++)
            LDM4(ah[mt], smb + SA_H + a_off + mt*(16*PITCHB) + ks*32);
#pragma unroll
        for (int np = 0; np < 2; np++)
            LDM4(bh[np], smb + SB_H + b_off + np*(16*PITCHB) + ks*32);
#pragma unroll
        for (int mt = 0; mt < 4; mt++)
#pragma unroll
            for (int nt = 0; nt < 4; nt++)
                MMA16816(c[mt][nt], ah[mt], bh[nt>>1][(nt&1)*2], bh[nt>>1][(nt&1)*2+1]);
        {
            u32 bl[2][4];
#pragma unroll
            for (int np = 0; np < 2; np++)
                LDM4(bl[np], smb + SB_L + b_off + np*(16*PITCHB) + ks*32);
#pragma unroll
            for (int mt = 0; mt < 4; mt++)
#pragma unroll
                for (int nt = 0; nt < 4; nt++)
                    MMA16816(c[mt][nt], ah[mt], bl[nt>>1][(nt&1)*2], bl[nt>>1][(nt&1)*2+1]);
        }
        {
            u32 al[4][4];
#pragma unroll
            for (int mt = 0; mt < 4; mt++)
                LDM4(al[mt], smb + SA_L + a_off + mt*(16*PITCHB) + ks*32);
#pragma unroll
            for (int mt = 0; mt < 4; mt++)
#pragma unroll
                for (int nt = 0; nt < 4; nt++)
                    MMA16816(c[mt][nt], al[mt], bh[nt>>1][(nt&1)*2], bh[nt>>1][(nt&1)*2+1]);
        }
    }
}

/* ------------------------------------------------------------------ */
/* K1: QKV GEMM via mma.sync; stores q/k/v as fp16 hi/lo pairs         */
/* ------------------------------------------------------------------ */
__global__ void __launch_bounds__(256, 2) k_qkv_t(const float* __restrict__ x,
        const float* __restrict__ wq, const float* __restrict__ wk,
        const float* __restrict__ wv){
    extern __shared__ char sm[];
    u32 smb = smem_u32(sm);
    int tid = threadIdx.x, wid = tid >> 5, lane = tid & 31;
    int t0 = blockIdx.x * 128;
    int b = t0 / NN, tl0 = t0 % NN;
    int oc = blockIdx.y;
    const float* W = (oc < 2) ? wq : (oc < 4 ? wk : wv);
    u32* dsth = (oc < 2) ? g_qh : (oc < 4 ? g_kh : g_vh);
    u32* dstl = (oc < 2) ? g_ql : (oc < 4 ? g_kl : g_vl);
    int or0 = (oc & 1) * 128;

    int wm = (wid >> 2) * 64, wn = (wid & 3) * 32;
    int tq  = lane * 4;
    int cg2 = wid * 2;
    int rb  = tid >> 4, cf = (tid & 15) * 4;

    float c[4][4][4];
#pragma unroll
    for (int mt = 0; mt < 4; mt++)
#pragma unroll
        for (int nt = 0; nt < 4; nt++)
#pragma unroll
            for (int r = 0; r < 4; r++) c[mt][nt][r] = 0.f;

    for (int ch = 0; ch < 4; ch++){
        int c0 = ch * 64;
#pragma unroll
        for (int u = 0; u < 4; u++){
            int cl = u*16 + cg2;
            const float* p = &x[((size_t)(b*256 + c0 + cl))*NN + tl0 + tq];
            float4 f0 = *(const float4*)p;
            float4 f1 = *(const float4*)(p + NN);
            const float* e0 = (const float*)&f0;
            const float* e1 = (const float*)&f1;
#pragma unroll
            for (int j = 0; j < 4; j++){
                u32 h, l;
                f16split2(e0[j], e1[j], h, l);
                u32 off = (u32)((tq + j)*PITCHB + cl*2);
                *(u32*)(sm + SA_H + off) = h;
                *(u32*)(sm + SA_L + off) = l;
            }
        }
#pragma unroll
        for (int s = 0; s < 8; s++){
            int row = rb + s*16;
            float4 f = *(const float4*)&W[(size_t)(or0 + row)*256 + c0 + cf];
            u32 h0, l0, h1, l1;
            f16split2(f.x, f.y, h0, l0);
            f16split2(f.z, f.w, h1, l1);
            u32 off = (u32)(row*PITCHB + cf*2);
            *(uint2*)(sm + SB_H + off) = make_uint2(h0, h1);
            *(uint2*)(sm + SB_L + off) = make_uint2(l0, l1);
        }
        __syncthreads();
        mma_chunk(smb, wm, wn, lane, c);
        __syncthreads();
    }

#pragma unroll
    for (int mt = 0; mt < 4; mt++){
#pragma unroll
        for (int nt = 0; nt < 4; nt++){
            int row = t0 + wm + mt*16 + (lane >> 2);
            int col = (or0 + wn + nt*8 + (lane & 3)*2) >> 1;
            u32 h, l;
            f16split2(c[mt][nt][0], c[mt][nt][1], h, l);
            dsth[(size_t)row*128 + col] = h;
            dstl[(size_t)row*128 + col] = l;
            f16split2(c[mt][nt][2], c[mt][nt][3], h, l);
            dsth[(size_t)(row+8)*128 + col] = h;
            dstl[(size_t)(row+8)*128 + col] = l;
        }
    }
}

/* ------------------------------------------------------------------ */
/* K2: global key-dash max per (b,h). hi-only fp16 MMA.                */
/* grid (72, 32), 256 thr. 128 tokens x 128 m per block.               */
/* ------------------------------------------------------------------ */
__global__ void __launch_bounds__(256) k_kmax(){
    __shared__ u32 projh[128*20];
    __shared__ u32 kth[128*20];
    __shared__ float red[256];
    int bh = blockIdx.y, b = bh >> 3, h = bh & 7;
    int n0 = blockIdx.x * 128;
    int t = threadIdx.x, wid = t >> 5, lane = t & 31;

    for (int i = t; i < 2048; i += 256)
        projh[(i>>4)*20 + (i&15)] = g_projh[i];
    for (int i = t; i < 2048; i += 256){
        int tok = i >> 4, cc = i & 15;
        kth[tok*20 + cc] = g_kh[(size_t)(b*NN + n0 + tok)*128 + h*16 + cc];
    }
    __syncthreads();

    int wm = (wid >> 1)*32, wn = (wid & 1)*64;
    float c[2][8][4];
#pragma unroll
    for (int mt = 0; mt < 2; mt++)
#pragma unroll
        for (int nt = 0; nt < 8; nt++)
#pragma unroll
            for (int r = 0; r < 4; r++) c[mt][nt][r] = 0.f;

    u32 smP = smem_u32(projh), smK = smem_u32(kth);
    u32 a_off = (u32)((wm + (lane & 15))*80 + (lane >> 4)*16);
    u32 b_off = (u32)((wn + (lane & 7) + ((lane >> 4) & 1)*8)*80 + ((lane >> 3) & 1)*16);
#pragma unroll
    for (int ks = 0; ks < 2; ks++){
        u32 a[2][4], bb[4][4];
#pragma unroll
        for (int mt = 0; mt < 2; mt++)
            LDM4(a[mt], smP + a_off + mt*(16*80) + ks*32);
#pragma unroll
        for (int np = 0; np < 4; np++)
            LDM4(bb[np], smK + b_off + np*(16*80) + ks*32);
#pragma unroll
        for (int mt = 0; mt < 2; mt++)
#pragma unroll
            for (int nt = 0; nt < 8; nt++)
                MMA16816(c[mt][nt], a[mt], bb[nt>>1][(nt&1)*2], bb[nt>>1][(nt&1)*2+1]);
    }
    float mx = -1e30f;
#pragma unroll
    for (int mt = 0; mt < 2; mt++)
#pragma unroll
        for (int nt = 0; nt < 8; nt++)
#pragma unroll
            for (int r = 0; r < 4; r++) mx = fmaxf(mx, c[mt][nt][r]);
    red[t] = mx;
    __syncthreads();
    for (int s = 128; s > 0; s >>= 1){
        if (t < (unsigned)s) red[t] = fmaxf(red[t], red[t + s]);
        __syncthreads();
    }
    if (t == 0) atomicMaxF(&g_kmax[bh], red[0]);
}

/* ------------------------------------------------------------------ */
/* K3: fused key features + ctx. grid (16, 32), 256 thr.               */
/* ------------------------------------------------------------------ */
#define CP_PROJH 0
#define CP_PROJL 10240
#define CP_KTH   20480
#define CP_KTL   25600
#define CP_KPSH  30720
#define CP_KPSL  49152
#define CP_VTH   67584
#define CP_VTL   74496
#define CP_VSGH  81408
#define CP_VSGL  85504
#define CP_DIAG  89600
#define CTX_SMEM 89856
#define CTX_SPLITS 16
#define CTX_TILES  9

__global__ void __launch_bounds__(256) k_ctx2(){
    extern __shared__ char sm[];
    u32 smb = smem_u32(sm);
    int bh = blockIdx.y, b = bh >> 3, h = bh & 7;
    int sp = blockIdx.x;
    int t = threadIdx.x, wid = t >> 5, lane = t & 31;
    float gmax = g_kmax[bh];

    u32* PJH = (u32*)(sm + CP_PROJH); u32* PJL = (u32*)(sm + CP_PROJL);
    u32* KTH = (u32*)(sm + CP_KTH);   u32* KTL = (u32*)(sm + CP_KTL);
    u32* VTH = (u32*)(sm + CP_VTH);   u32* VTL = (u32*)(sm + CP_VTL);
    u32* VSH = (u32*)(sm + CP_VSGH);  u32* VSL = (u32*)(sm + CP_VSGL);
    float* DIAG = (float*)(sm + CP_DIAG);

    for (int i = t; i < 2048; i += 256){
        PJH[(i>>4)*20 + (i&15)] = g_projh[i];
        PJL[(i>>4)*20 + (i&15)] = g_projl[i];
    }
    /* vt pad rows 32..47: row32 = ones, rest zero */
    for (int i = t; i < 1024; i += 256){
        int mat = i >> 9, rem = i & 511;
        int j = 32 + (rem >> 5), tp = rem & 31;
        u32 v = (j == 32 && mat == 0) ? 0x3C003C00u : 0u;
        ((mat == 0) ? VTH : VTL)[j*36 + tp] = v;
    }

    /* mma1 geometry: M=128 m, N=64 tok */
    int wm1 = (wid >> 1)*32, wn1 = (wid & 1)*32;
    u32 a1_off = (u32)((wm1 + (lane & 15))*80 + (lane >> 4)*16);
    u32 b1_off = (u32)((wn1 + (lane & 7) + ((lane >> 4) & 1)*8)*80 + ((lane >> 3) & 1)*16);
    /* mma2 geometry: M=128 m, N=48 j, K=64 tok */
    int wm2 = (wid >> 1)*32, wn2 = (wid & 1)*24;
    u32 a2_off = (u32)((wm2 + (lane & 15))*144 + (lane >> 4)*16);
    u32 b2_off = (u32)((wn2 + (lane & 7) + ((lane >> 4) & 1)*8)*144 + ((lane >> 3) & 1)*16);

    float c2[2][3][4];
#pragma unroll
    for (int mt = 0; mt < 2; mt++)
#pragma unroll
        for (int nt = 0; nt < 3; nt++)
#pragma unroll
            for (int r = 0; r < 4; r++) c2[mt][nt][r] = 0.f;

    for (int it = 0; it < CTX_TILES; it++){
        int n0 = sp*(CTX_TILES*64) + it*64;
        /* load k tile + v stage (hi/lo) */
        for (int i = t; i < 1024; i += 256){
            int tok = i >> 4, cc = i & 15;
            size_t g = (size_t)(b*NN + n0 + tok)*128 + h*16 + cc;
            KTH[tok*20 + cc] = g_kh[g];
            KTL[tok*20 + cc] = g_kl[g];
            VSH[tok*16 + cc] = g_vh[g];
            VSL[tok*16 + cc] = g_vl[g];
        }
        __syncthreads();
        /* diag per token + v transpose */
        if (t < 64){
            float sq = 0.f;
#pragma unroll
            for (int i = 0; i < 16; i++){
                float2 v = h2f(KTH[t*20 + i], KTL[t*20 + i]);
                sq += v.x*v.x + v.y*v.y;
            }
            DIAG[t] = HALF_NRM2 * sq;
        }
        for (int i = t; i < 2048; i += 256){
            int mat = i >> 10, rem = i & 1023;
            int j = rem >> 5, tp = rem & 31;
            int tok0 = tp*2;
            u32* src = mat ? VSL : VSH;
            u32 w0 = src[tok0*16 + (j >> 1)];
            u32 w1 = src[(tok0+1)*16 + (j >> 1)];
            u32 h0 = (j & 1) ? (w0 >> 16) : (w0 & 0xFFFF);
            u32 h1 = (j & 1) ? (w1 >> 16) : (w1 & 0xFFFF);
            (mat ? VTL : VTH)[j*36 + tp] = h0 | (h1 << 16);
        }
        __syncthreads();

        /* mma1: dash = projn . k  (3-pass split) */
        float c1[2][4][4];
#pragma unroll
        for (int mt = 0; mt < 2; mt++)
#pragma unroll
            for (int nt = 0; nt < 4; nt++)
#pragma unroll
                for (int r = 0; r < 4; r++) c1[mt][nt][r] = 0.f;
#pragma unroll
        for (int ks = 0; ks < 2; ks++){
            u32 ah[2][4], bhh[2][4];
#pragma unroll
            for (int mt = 0; mt < 2; mt++)
                LDM4(ah[mt], smb + CP_PROJH + a1_off + mt*(16*80) + ks*32);
#pragma unroll
            for (int np = 0; np < 2; np++)
                LDM4(bhh[np], smb + CP_KTH + b1_off + np*(16*80) + ks*32);
#pragma unroll
            for (int mt = 0; mt < 2; mt++)
#pragma unroll
                for (int nt = 0; nt < 4; nt++)
                    MMA16816(c1[mt][nt], ah[mt], bhh[nt>>1][(nt&1)*2], bhh[nt>>1][(nt&1)*2+1]);
            {
                u32 bl[2][4];
#pragma unroll
                for (int np = 0; np < 2; np++)
                    LDM4(bl[np], smb + CP_KTL + b1_off + np*(16*80) + ks*32);
#pragma unroll
                for (int mt = 0; mt < 2; mt++)
#pragma unroll
                    for (int nt = 0; nt < 4; nt++)
                        MMA16816(c1[mt][nt], ah[mt], bl[nt>>1][(nt&1)*2], bl[nt>>1][(nt&1)*2+1]);
            }
            {
                u32 al[2][4];
#pragma unroll
                for (int mt = 0; mt < 2; mt++)
                    LDM4(al[mt], smb + CP_PROJL + a1_off + mt*(16*80) + ks*32);
#pragma unroll
                for (int mt = 0; mt < 2; mt++)
#pragma unroll
                    for (int nt = 0; nt < 4; nt++)
                        MMA16816(c1[mt][nt], al[mt], bhh[nt>>1][(nt&1)*2], bhh[nt>>1][(nt&1)*2+1]);
            }
        }
        /* exp -> kps (hi/lo) */
        u32* KPH = (u32*)(sm + CP_KPSH);
        u32* KPL = (u32*)(sm + CP_KPSL);
#pragma unroll
        for (int mt = 0; mt < 2; mt++){
#pragma unroll
            for (int nt = 0; nt < 4; nt++){
                int col = wn1 + nt*8 + (lane & 3)*2;
                float d0 = DIAG[col] + gmax, d1 = DIAG[col+1] + gmax;
                int r0 = wm1 + mt*16 + (lane >> 2);
                float v0 = KP_RATIO*(__expf(c1[mt][nt][0] - d0) + EPSF);
                float v1 = KP_RATIO*(__expf(c1[mt][nt][1] - d1) + EPSF);
                float v2 = KP_RATIO*(__expf(c1[mt][nt][2] - d0) + EPSF);
                float v3 = KP_RATIO*(__expf(c1[mt][nt][3] - d1) + EPSF);
                u32 hh, ll;
                f16split2(v0, v1, hh, ll);
                KPH[r0*36 + (col>>1)] = hh; KPL[r0*36 + (col>>1)] = ll;
                f16split2(v2, v3, hh, ll);
                KPH[(r0+8)*36 + (col>>1)] = hh; KPL[(r0+8)*36 + (col>>1)] = ll;
            }
        }
        __syncthreads();

        /* mma2: ctx += kps . vt^T (3-pass split), K=64 tok */
#pragma unroll
        for (int ks = 0; ks < 4; ks++){
            u32 ah[2][4], bhh[2][4];
#pragma unroll
            for (int mt = 0; mt < 2; mt++)
                LDM4(ah[mt], smb + CP_KPSH + a2_off + mt*(16*144) + ks*32);
#pragma unroll
            for (int np = 0; np < 2; np++)
                LDM4(bhh[np], smb + CP_VTH + b2_off + np*(16*144) + ks*32);
#pragma unroll
            for (int mt = 0; mt < 2; mt++)
#pragma unroll
                for (int nt = 0; nt < 3; nt++)
                    MMA16816(c2[mt][nt], ah[mt], bhh[nt>>1][(nt&1)*2], bhh[nt>>1][(nt&1)*2+1]);
            {
                u32 bl[2][4];
#pragma unroll
                for (int np = 0; np < 2; np++)
                    LDM4(bl[np], smb + CP_VTL + b2_off + np*(16*144) + ks*32);
#pragma unroll
                for (int mt = 0; mt < 2; mt++)
#pragma unroll
                    for (int nt = 0; nt < 3; nt++)
                        MMA16816(c2[mt][nt], ah[mt], bl[nt>>1][(nt&1)*2], bl[nt>>1][(nt&1)*2+1]);
            }
            {
                u32 al[2][4];
#pragma unroll
                for (int mt = 0; mt < 2; mt++)
                    LDM4(al[mt], smb + CP_KPSL + a2_off + mt*(16*144) + ks*32);
#pragma unroll
                for (int mt = 0; mt < 2; mt++)
#pragma unroll
                    for (int nt = 0; nt < 3; nt++)
                        MMA16816(c2[mt][nt], al[mt], bhh[nt>>1][(nt&1)*2], bhh[nt>>1][(nt&1)*2+1]);
            }
        }
        __syncthreads();
    }

    /* atomics into g_ctx */
#pragma unroll
    for (int mt = 0; mt < 2; mt++){
#pragma unroll
        for (int nt = 0; nt < 3; nt++){
            int m = wm2 + mt*16 + (lane >> 2);
            int n = wn2 + nt*8 + (lane & 3)*2;
            size_t base = ((size_t)bh*MF + m)*33;
            if (n < 33)   atomicAdd(&g_ctx[base + n],     c2[mt][nt][0]);
            if (n+1 < 33) atomicAdd(&g_ctx[base + n + 1], c2[mt][nt][1]);
            if (n < 33)   atomicAdd(&g_ctx[base + 264 + n],     c2[mt][nt][2]);
            if (n+1 < 33) atomicAdd(&g_ctx[base + 264 + n + 1], c2[mt][nt][3]);
        }
    }
}

/* ------------------------------------------------------------------ */
/* K4: fused query features + qp@ctx + d_inv. grid (144, 32), 256 thr. */
/* ------------------------------------------------------------------ */
#define QP_PROJH 0
#define QP_PROJL 10240
#define QP_QTH   20480
#define QP_QTL   25600
#define QP_QPSH  30720
#define QP_QPSL  49152
#define QP_CTH   67584
#define QP_CTL   84992
#define QP_PM    102400
#define QP_RMAX  103424
#define QP_DIAG  103680
#define QP_STG   QP_QPSH     /* overlay: stage written after mma2 */
#define QA_SMEM  103936

__global__ void __launch_bounds__(256) k_qattn2(){
    extern __shared__ char sm[];
    u32 smb = smem_u32(sm);
    int bh = blockIdx.y, b = bh >> 3, h = bh & 7;
    int n0 = blockIdx.x * 64;
    int t = threadIdx.x, wid = t >> 5, lane = t & 31;

    u32* PJH = (u32*)(sm + QP_PROJH); u32* PJL = (u32*)(sm + QP_PROJL);
    u32* QTH = (u32*)(sm + QP_QTH);   u32* QTL = (u32*)(sm + QP_QTL);
    u32* CTH = (u32*)(sm + QP_CTH);   u32* CTL = (u32*)(sm + QP_CTL);
    float* PM = (float*)(sm + QP_PM);
    float* RMAX = (float*)(sm + QP_RMAX);
    float* DIAG = (float*)(sm + QP_DIAG);

    for (int i = t; i < 2048; i += 256){
        PJH[(i>>4)*20 + (i&15)] = g_projh[i];
        PJL[(i>>4)*20 + (i&15)] = g_projl[i];
    }
    for (int i = t; i < 1024; i += 256){
        int tok = i >> 4, cc = i & 15;
        size_t g = (size_t)(b*NN + n0 + tok)*128 + h*16 + cc;
        QTH[tok*20 + cc] = g_qh[g];
        QTL[tok*20 + cc] = g_ql[g];
    }
    /* ctxT [j=64][m=128] half pairs, j>=33 zero */
    for (int i = t; i < 4096; i += 256){
        int j = i >> 6, mp = i & 63;
        float a = 0.f, bb = 0.f;
        if (j < 33){
            a  = g_ctx[((size_t)bh*MF + mp*2)*33 + j];
            bb = g_ctx[((size_t)bh*MF + mp*2 + 1)*33 + j];
        }
        u32 hh, ll;
        f16split2(a, bb, hh, ll);
        CTH[j*68 + mp] = hh; CTL[j*68 + mp] = ll;
    }
    __syncthreads();
    if (t < 64){
        float sq = 0.f;
#pragma unroll
        for (int i = 0; i < 16; i++){
            float2 v = h2f(QTH[t*20 + i], QTL[t*20 + i]);
            sq += v.x*v.x + v.y*v.y;
        }
        DIAG[t] = HALF_NRM2 * sq;
    }
    __syncthreads();

    /* mma1: dash[m][tok], M=128, N=64, K=32, 3-pass */
    int wm1 = (wid >> 1)*32, wn1 = (wid & 1)*32;
    u32 a1_off = (u32)((wm1 + (lane & 15))*80 + (lane >> 4)*16);
    u32 b1_off = (u32)((wn1 + (lane & 7) + ((lane >> 4) & 1)*8)*80 + ((lane >> 3) & 1)*16);
    float c1[2][4][4];
#pragma unroll
    for (int mt = 0; mt < 2; mt++)
#pragma unroll
        for (int nt = 0; nt < 4; nt++)
#pragma unroll
            for (int r = 0; r < 4; r++) c1[mt][nt][r] = 0.f;
#pragma unroll
    for (int ks = 0; ks < 2; ks++){
        u32 ah[2][4], bhh[2][4];
#pragma unroll
        for (int mt = 0; mt < 2; mt++)
            LDM4(ah[mt], smb + QP_PROJH + a1_off + mt*(16*80) + ks*32);
#pragma unroll
        for (int np = 0; np < 2; np++)
            LDM4(bhh[np], smb + QP_QTH + b1_off + np*(16*80) + ks*32);
#pragma unroll
        for (int mt = 0; mt < 2; mt++)
#pragma unroll
            for (int nt = 0; nt < 4; nt++)
                MMA16816(c1[mt][nt], ah[mt], bhh[nt>>1][(nt&1)*2], bhh[nt>>1][(nt&1)*2+1]);
        {
            u32 bl[2][4];
#pragma unroll
            for (int np = 0; np < 2; np++)
                LDM4(bl[np], smb + QP_QTL + b1_off + np*(16*80) + ks*32);
#pragma unroll
            for (int mt = 0; mt < 2; mt++)
#pragma unroll
                for (int nt = 0; nt < 4; nt++)
                    MMA16816(c1[mt][nt], ah[mt], bl[nt>>1][(nt&1)*2], bl[nt>>1][(nt&1)*2+1]);
        }
        {
            u32 al[2][4];
#pragma unroll
            for (int mt = 0; mt < 2; mt++)
                LDM4(al[mt], smb + QP_PROJL + a1_off + mt*(16*80) + ks*32);
#pragma unroll
            for (int mt = 0; mt < 2; mt++)
#pragma unroll
                for (int nt = 0; nt < 4; nt++)
                    MMA16816(c1[mt][nt], al[mt], bhh[nt>>1][(nt&1)*2], bhh[nt>>1][(nt&1)*2+1]);
        }
    }

    /* per-token max: reduce over m within warp via shfl, then across warp rows */
#pragma unroll
    for (int nt = 0; nt < 4; nt++){
        float me = fmaxf(fmaxf(c1[0][nt][0], c1[0][nt][2]),
                         fmaxf(c1[1][nt][0], c1[1][nt][2]));
        float mo = fmaxf(fmaxf(c1[0][nt][1], c1[0][nt][3]),
                         fmaxf(c1[1][nt][1], c1[1][nt][3]));
#pragma unroll
        for (int s = 4; s < 32; s <<= 1){
            me = fmaxf(me, __shfl_xor_sync(0xFFFFFFFF, me, s));
            mo = fmaxf(mo, __shfl_xor_sync(0xFFFFFFFF, mo, s));
        }
        if ((lane >> 2) == 0){
            int col = wn1 + nt*8 + (lane & 3)*2;
            PM[(wid >> 1)*64 + col]     = me;
            PM[(wid >> 1)*64 + col + 1] = mo;
        }
    }
    __syncthreads();
    if (t < 64){
        float mx = PM[t];
        mx = fmaxf(mx, PM[64 + t]);
        mx = fmaxf(mx, PM[128 + t]);
        mx = fmaxf(mx, PM[192 + t]);
        RMAX[t] = mx;
    }
    __syncthreads();

    /* exp -> qps [m][tok] hi/lo */
    {
        u32* QPH = (u32*)(sm + QP_QPSH);
        u32* QPL = (u32*)(sm + QP_QPSL);
#pragma unroll
        for (int mt = 0; mt < 2; mt++){
#pragma unroll
            for (int nt = 0; nt < 4; nt++){
                int col = wn1 + nt*8 + (lane & 3)*2;
                float d0 = DIAG[col] + RMAX[col], d1 = DIAG[col+1] + RMAX[col+1];
                int r0 = wm1 + mt*16 + (lane >> 2);
                float v0 = QP_RATIO*(__expf(c1[mt][nt][0] - d0) + EPSF);
                float v1 = QP_RATIO*(__expf(c1[mt][nt][1] - d1) + EPSF);
                float v2 = QP_RATIO*(__expf(c1[mt][nt][2] - d0) + EPSF);
                float v3 = QP_RATIO*(__expf(c1[mt][nt][3] - d1) + EPSF);
                u32 hh, ll;
                f16split2(v0, v1, hh, ll);
                QPH[r0*36 + (col>>1)] = hh; QPL[r0*36 + (col>>1)] = ll;
                f16split2(v2, v3, hh, ll);
                QPH[(r0+8)*36 + (col>>1)] = hh; QPL[(r0+8)*36 + (col>>1)] = ll;
            }
        }
    }
    __syncthreads();

    /* mma2: outT[j][tok] = ctxT . qps^T   M=64 j, N=64 tok, K=128 m */
    int wm2 = (wid >> 1)*16, wn2 = (wid & 1)*32;
    u32 a2_off = (u32)((wm2 + (lane & 15))*272 + (lane >> 4)*16);
    float c2[4][4];
#pragma unroll
    for (int nt = 0; nt < 4; nt++)
#pragma unroll
        for (int r = 0; r < 4; r++) c2[nt][r] = 0.f;
#pragma unroll
    for (int ks = 0; ks < 8; ks++){
        u32 ah[4], al[4], bt[2][4], btl[2][4];
        LDM4(ah, smb + QP_CTH + a2_off + ks*32);
        LDM4(al, smb + QP_CTL + a2_off + ks*32);
        /* B = qps via ldmatrix.trans from [m][tok] */
        u32 rowb = (u32)((ks*16 + (lane & 7) + ((lane >> 3) & 1)*8)*144);
#pragma unroll
        for (int np = 0; np < 2; np++){
            u32 colb = (u32)((wn2 + np*16 + ((lane >> 4) & 1)*8)*2);
            LDM4T(bt[np],  smb + QP_QPSH + rowb + colb);
            LDM4T(btl[np], smb + QP_QPSL + rowb + colb);
        }
#pragma unroll
        for (int nt = 0; nt < 4; nt++){
            MMA16816(c2[nt], ah, bt[nt>>1][(nt&1)*2],  bt[nt>>1][(nt&1)*2+1]);
            MMA16816(c2[nt], ah, btl[nt>>1][(nt&1)*2], btl[nt>>1][(nt&1)*2+1]);
            MMA16816(c2[nt], al, bt[nt>>1][(nt&1)*2],  bt[nt>>1][(nt&1)*2+1]);
        }
    }
    __syncthreads();

    /* stage outT (j<=32) */
    float* STG = (float*)(sm + QP_STG);   /* [34][68] */
#pragma unroll
    for (int nt = 0; nt < 4; nt++){
        int j = wm2 + (lane >> 2);
        int tok = wn2 + nt*8 + (lane & 3)*2;
        if (j <= 32){
            STG[j*68 + tok]     = c2[nt][0];
            STG[j*68 + tok + 1] = c2[nt][1];
        }
        if (j + 8 <= 32){
            STG[(j+8)*68 + tok]     = c2[nt][2];
            STG[(j+8)*68 + tok + 1] = c2[nt][3];
        }
    }
    __syncthreads();

    /* write g_attn[tok][j] with d_inv */
    {
        int tok = t >> 2, jb = (t & 3)*8;
        float inv = 1.0f / STG[32*68 + tok];
        float vals[8];
#pragma unroll
        for (int jj = 0; jj < 8; jj++)
            vals[jj] = STG[(jb + jj)*68 + tok] * inv;
        float* dst = &g_attn[((size_t)(b*NN + n0 + tok))*256 + h*32 + jb];
        *(float4*)dst       = make_float4(vals[0], vals[1], vals[2], vals[3]);
        *(float4*)(dst + 4) = make_float4(vals[4], vals[5], vals[6], vals[7]);
    }
}

/* ------------------------------------------------------------------ */
/* K5: final GEMM via mma.sync fp16-split; transposed store + bias.    */
/* ------------------------------------------------------------------ */
__global__ void __launch_bounds__(256, 2) k_final_t(float* __restrict__ out){
    extern __shared__ char sm[];
    u32 smb = smem_u32(sm);
    int tid = threadIdx.x, wid = tid >> 5, lane = tid & 31;
    int t0 = blockIdx.x * 128;
    int b = t0 / NN, tl0 = t0 % NN;
    int o0 = blockIdx.y * 128;

    int wm = (wid >> 2) * 64, wn = (wid & 3) * 32;
    int rb = tid >> 4, cf = (tid & 15) * 4;

    float c[4][4][4];
#pragma unroll
    for (int mt = 0; mt < 4; mt++)
#pragma unroll
        for (int nt = 0; nt < 4; nt++)
#pragma unroll
            for (int r = 0; r < 4; r++) c[mt][nt][r] = 0.f;

    for (int ch = 0; ch < 4; ch++){
        int c0 = ch * 64;
#pragma unroll
        for (int s = 0; s < 8; s++){
            int row = rb + s*16;
            float4 fa = *(const float4*)&g_attn[(size_t)(t0 + row)*256 + c0 + cf];
            float4 fb = *(const float4*)&g_Wc[(size_t)(o0 + row)*256 + c0 + cf];
            u32 h0, l0, h1, l1;
            u32 off = (u32)(row*PITCHB + cf*2);
            f16split2(fa.x, fa.y, h0, l0);
            f16split2(fa.z, fa.w, h1, l1);
            *(uint2*)(sm + SA_H + off) = make_uint2(h0, h1);
            *(uint2*)(sm + SA_L + off) = make_uint2(l0, l1);
            f16split2(fb.x, fb.y, h0, l0);
            f16split2(fb.z, fb.w, h1, l1);
            *(uint2*)(sm + SB_H + off) = make_uint2(h0, h1);
            *(uint2*)(sm + SB_L + off) = make_uint2(l0, l1);
        }
        __syncthreads();
        mma_chunk(smb, wm, wn, lane, c);
        __syncthreads();
    }

    float* stage = (float*)sm;
#pragma unroll
    for (int mt = 0; mt < 4; mt++){
#pragma unroll
        for (int nt = 0; nt < 4; nt++){
            int r = wm + mt*16 + (lane >> 2);
            int cc = wn + nt*8 + (lane & 3)*2;
            stage[cc*132 + r]         = c[mt][nt][0];
            stage[(cc+1)*132 + r]     = c[mt][nt][1];
            stage[cc*132 + r + 8]     = c[mt][nt][2];
            stage[(cc+1)*132 + r + 8] = c[mt][nt][3];
        }
    }
    __syncthreads();
#pragma unroll
    for (int i2 = 0; i2 < 16; i2++){
        int idx = i2*256 + tid;
        int cc = idx >> 5, t4 = (idx & 31) * 4;
        int o = o0 + cc;
        float bias = g_bc[o];
        float4 v = *(float4*)&stage[cc*132 + t4];
        v.x += bias; v.y += bias; v.z += bias; v.w += bias;
        *(float4*)&out[((size_t)b*256 + o)*NN + tl0 + t4] = v;
    }
}

/* ------------------------------------------------------------------ */
extern "C" void kernel_launch(void* const* d_in, const int* in_sizes, int n_in,
                              void* d_out, int out_size){
    const float* x    = (const float*)d_in[0];
    const float* wq   = (const float*)d_in[1];
    const float* wk   = (const float*)d_in[2];
    const float* wv   = (const float*)d_in[3];
    const float* wo   = (const float*)d_in[4];
    const float* bo   = (const float*)d_in[5];
    const float* proj = (const float*)d_in[6];
    const float* wp   = (const float*)d_in[7];
    const float* bp   = (const float*)d_in[8];
    float* out = (float*)d_out;

    cudaFuncSetAttribute(k_qkv_t,   cudaFuncAttributeMaxDynamicSharedMemorySize, G2_SMEM);
    cudaFuncSetAttribute(k_final_t, cudaFuncAttributeMaxDynamicSharedMemorySize, G2_SMEM);
    cudaFuncSetAttribute(k_ctx2,    cudaFuncAttributeMaxDynamicSharedMemorySize, CTX_SMEM);
    cudaFuncSetAttribute(k_qattn2,  cudaFuncAttributeMaxDynamicSharedMemorySize, QA_SMEM);

    k_prep<<<256, 256>>>(wo, bo, wp, bp);
    k_prep_proj<<<8, 256>>>(proj);
    k_init<<<(32*MF*33 + 255)/256, 256>>>();
    k_qkv_t<<<dim3(TT/128, 6), 256, G2_SMEM>>>(x, wq, wk, wv);
    k_kmax<<<dim3(NN/128, 32), 256>>>();
    k_ctx2<<<dim3(CTX_SPLITS, 32), 256, CTX_SMEM>>>();
    k_qattn2<<<dim3(NN/64, 32), 256, QA_SMEM>>>();
    k_final_t<<<dim3(TT/128, 2), 256, G2_SMEM>>>(out);
}

// round 6
// speedup vs baseline: 1.6739x; 1.0653x over previous
#include <cuda_runtime.h>
#include <cuda_fp16.h>
#include <math.h>

#define BB 4
#define CC 256
#define NHEAD 8
#define DHEAD 32
#define MF 128
#define NN 9216
#define TT (BB*NN)   /* 36864 */

#define NRM       0.4204482076268573f     /* 32^-0.25 */
#define HALF_NRM2 0.08838834764831845f    /* 0.5 * 32^-0.5 */
#define RATIO     0.08838834764831845f    /* 128^-0.5 */
#define EPSF      1e-4f
#define KP_SCALE  64.0f
#define QP_SCALE  64.0f
#define KP_RATIO  (RATIO*KP_SCALE)
#define QP_RATIO  (RATIO*QP_SCALE)

typedef unsigned long long u64;
typedef unsigned int u32;

/* ---------------- mma.sync helpers ---------------- */
__device__ __forceinline__ u32 smem_u32(const void* p){
    u32 a; asm("{ .reg .u64 t; cvta.to.shared.u64 t, %1; cvt.u32.u64 %0, t; }"
               : "=r"(a) : "l"(p)); return a;
}
#define LDM4(r, a) \
    asm volatile("ldmatrix.sync.aligned.m8n8.x4.shared.b16 {%0,%1,%2,%3}, [%4];" \
        : "=r"((r)[0]),"=r"((r)[1]),"=r"((r)[2]),"=r"((r)[3]) : "r"(a))
#define LDM4T(r, a) \
    asm volatile("ldmatrix.sync.aligned.m8n8.x4.trans.shared.b16 {%0,%1,%2,%3}, [%4];" \
        : "=r"((r)[0]),"=r"((r)[1]),"=r"((r)[2]),"=r"((r)[3]) : "r"(a))
#define MMA16816(c, a, b0, b1) \
    asm volatile("mma.sync.aligned.m16n8k16.row.col.f32.f16.f16.f32 " \
        "{%0,%1,%2,%3}, {%4,%5,%6,%7}, {%8,%9}, {%0,%1,%2,%3};" \
        : "+f"((c)[0]),"+f"((c)[1]),"+f"((c)[2]),"+f"((c)[3]) \
        : "r"((a)[0]),"r"((a)[1]),"r"((a)[2]),"r"((a)[3]), "r"(b0),"r"(b1))

__device__ __forceinline__ void f16split2(float a, float b, u32 &h, u32 &l){
    __half2 hh = __floats2half2_rn(a, b);
    float2 bk = __half22float2(hh);
    __half2 ll = __floats2half2_rn(a - bk.x, b - bk.y);
    h = *(u32*)&hh; l = *(u32*)&ll;
}
__device__ __forceinline__ float2 h2f(u32 h, u32 l){
    float2 a = __half22float2(*(__half2*)&h);
    float2 b = __half22float2(*(__half2*)&l);
    return make_float2(a.x + b.x, a.y + b.y);
}

/* qkv/final GEMM smem: 128 rows x 64 halves, pitch 144 B */
#define PITCHB 144
#define SA_H 0
#define SA_L 18432
#define SB_H 36864
#define SB_L 55296
#define G2_SMEM 73728

/* ---------------- scratch ---------------- */
__device__ u32 g_xh[(size_t)TT*128];
__device__ u32 g_xl[(size_t)TT*128];
__device__ u32 g_qh[(size_t)TT*128];
__device__ u32 g_ql[(size_t)TT*128];
__device__ u32 g_kh[(size_t)TT*128];
__device__ u32 g_kl[(size_t)TT*128];
__device__ u32 g_vh[(size_t)TT*128];
__device__ u32 g_vl[(size_t)TT*128];
__device__ u32 g_ah[(size_t)TT*128];
__device__ u32 g_al[(size_t)TT*128];
__device__ u32 g_wh[3*256*128];
__device__ u32 g_wl[3*256*128];
__device__ u32 g_wch[256*128];
__device__ u32 g_wcl[256*128];
__device__ float g_kmax[32];
__device__ float g_ctx[32*MF*33];
__device__ float g_Wc[CC*CC];
__device__ float g_bc[CC];
__device__ u32 g_projh[2048];   /* [m=128][pair=16], NRM folded */
__device__ u32 g_projl[2048];

__device__ __forceinline__ void atomicMaxF(float* a, float v){
    int old = __float_as_int(*a);
    while (__int_as_float(old) < v){
        int cur = atomicCAS((int*)a, old, __float_as_int(v));
        if (cur == old) break;
        old = cur;
    }
}

/* ------------------------------------------------------------------ */
__global__ void k_prep(const float* __restrict__ wo, const float* __restrict__ bo,
                       const float* __restrict__ wp, const float* __restrict__ bp){
    int o2 = blockIdx.x;
    int c  = threadIdx.x;
    float s = 0.f;
    for (int o = 0; o < 256; o++) s += wp[o2*256 + o] * wo[o*256 + c];
    g_Wc[o2*256 + c] = s;
    if (c == 0){
        float sb = 0.f;
        for (int o = 0; o < 256; o++) sb += wp[o2*256 + o] * bo[o];
        g_bc[o2] = sb + bp[o2];
    }
}

__global__ void k_prep_proj(const float* __restrict__ proj){
    int i = blockIdx.x*256 + threadIdx.x;   /* 2048 */
    int m = i >> 4, p = i & 15;
    float a = proj[m*32 + p*2]     * NRM;
    float b = proj[m*32 + p*2 + 1] * NRM;
    u32 h, l;
    f16split2(a, b, h, l);
    g_projh[i] = h; g_projl[i] = l;
}

/* split wq/wk/wv: 3*256 rows x 128 pairs */
__global__ void k_prep_w(const float* __restrict__ wq, const float* __restrict__ wk,
                         const float* __restrict__ wv){
    int i = blockIdx.x*256 + threadIdx.x;   /* 98304 */
    int oc = i >> 15, rem = i & 32767;
    int row = rem >> 7, p = rem & 127;
    const float* W = (oc == 0) ? wq : (oc == 1 ? wk : wv);
    u32 h, l;
    f16split2(W[row*256 + p*2], W[row*256 + p*2 + 1], h, l);
    g_wh[i] = h; g_wl[i] = l;
}

/* split folded Wc: 256 rows x 128 pairs (runs after k_prep) */
__global__ void k_prep_wc(){
    int i = blockIdx.x*256 + threadIdx.x;   /* 32768 */
    int row = i >> 7, p = i & 127;
    u32 h, l;
    f16split2(g_Wc[row*256 + p*2], g_Wc[row*256 + p*2 + 1], h, l);
    g_wch[i] = h; g_wcl[i] = l;
}

__global__ void k_init(){
    int i = blockIdx.x*blockDim.x + threadIdx.x;
    if (i < 32*MF*33) g_ctx[i] = 0.f;
    if (i < 32) g_kmax[i] = -1e30f;
}

/* ------------------------------------------------------------------ */
/* K_xcvt: transpose+split x -> g_xh/g_xl [token][128 pairs]           */
/* grid 288, 256 thr, 128 tokens x 256 channels per block              */
/* ------------------------------------------------------------------ */
__global__ void __launch_bounds__(256) k_xcvt(const float* __restrict__ x){
    __shared__ u32 sh[128*33];
    __shared__ u32 sl[128*33];
    int tid = threadIdx.x, wid = tid >> 5, lane = tid & 31;
    int t0 = blockIdx.x * 128;
    int b = t0 / NN, tl0 = t0 % NN;
    int tq = lane * 4, cg2 = wid * 2;

    for (int ch = 0; ch < 4; ch++){
        int c0 = ch * 64;
#pragma unroll
        for (int u = 0; u < 4; u++){
            int cl = u*16 + cg2;
            const float* p = &x[((size_t)(b*256 + c0 + cl))*NN + tl0 + tq];
            float4 f0 = *(const float4*)p;
            float4 f1 = *(const float4*)(p + NN);
            const float* e0 = (const float*)&f0;
            const float* e1 = (const float*)&f1;
#pragma unroll
            for (int j = 0; j < 4; j++){
                u32 h, l;
                f16split2(e0[j], e1[j], h, l);
                sh[(tq + j)*33 + (cl >> 1)] = h;
                sl[(tq + j)*33 + (cl >> 1)] = l;
            }
        }
        __syncthreads();
#pragma unroll
        for (int r = 0; r < 16; r++){
            int i = r*256 + tid;
            int row = i >> 5, p = i & 31;
            size_t g = (size_t)(t0 + row)*128 + ch*32 + p;
            g_xh[g] = sh[row*33 + p];
            g_xl[g] = sl[row*33 + p];
        }
        __syncthreads();
    }
}

/* ------------------------------------------------------------------ */
/* shared mma micro-body for qkv/final                                 */
/* ------------------------------------------------------------------ */
__device__ __forceinline__ void mma_chunk(u32 smb, int wm, int wn, int lane,
                                          float c[4][4][4]){
    u32 a_off = (u32)((wm + (lane & 15))*PITCHB + (lane >> 4)*16);
    u32 b_off = (u32)((wn + (lane & 7) + ((lane >> 4) & 1)*8)*PITCHB
                      + ((lane >> 3) & 1)*16);
#pragma unroll
    for (int ks = 0; ks < 4; ks++){
        u32 ah[4][4], bh[2][4];
#pragma unroll
        for (int mt = 0; mt < 4; mt++)
            LDM4(ah[mt], smb + SA_H + a_off + mt*(16*PITCHB) + ks*32);
#pragma unroll
        for (int np = 0; np < 2; np++)
            LDM4(bh[np], smb + SB_H + b_off + np*(16*PITCHB) + ks*32);
#pragma unroll
        for (int mt = 0; mt < 4; mt++)
#pragma unroll
            for (int nt = 0; nt < 4; nt++)
                MMA16816(c[mt][nt], ah[mt], bh[nt>>1][(nt&1)*2], bh[nt>>1][(nt&1)*2+1]);
        {
            u32 bl[2][4];
#pragma unroll
            for (int np = 0; np < 2; np++)
                LDM4(bl[np], smb + SB_L + b_off + np*(16*PITCHB) + ks*32);
#pragma unroll
            for (int mt = 0; mt < 4; mt++)
#pragma unroll
                for (int nt = 0; nt < 4; nt++)
                    MMA16816(c[mt][nt], ah[mt], bl[nt>>1][(nt&1)*2], bl[nt>>1][(nt&1)*2+1]);
        }
        {
            u32 al[4][4];
#pragma unroll
            for (int mt = 0; mt < 4; mt++)
                LDM4(al[mt], smb + SA_L + a_off + mt*(16*PITCHB) + ks*32);
#pragma unroll
            for (int mt = 0; mt < 4; mt++)
#pragma unroll
                for (int nt = 0; nt < 4; nt++)
                    MMA16816(c[mt][nt], al[mt], bh[nt>>1][(nt&1)*2], bh[nt>>1][(nt&1)*2+1]);
        }
    }
}

/* ------------------------------------------------------------------ */
/* K1: QKV GEMM — pure fp16 copies + mma. grid (6, 288), 256 thr.      */
/* ------------------------------------------------------------------ */
__global__ void __launch_bounds__(256, 2) k_qkv_t(){
    extern __shared__ char sm[];
    u32 smb = smem_u32(sm);
    int tid = threadIdx.x, wid = tid >> 5, lane = tid & 31;
    int oc = blockIdx.x;
    int t0 = blockIdx.y * 128;
    int wsel = oc >> 1;
    u32* dsth = (oc < 2) ? g_qh : (oc < 4 ? g_kh : g_vh);
    u32* dstl = (oc < 2) ? g_ql : (oc < 4 ? g_kl : g_vl);
    int or0 = (oc & 1) * 128;

    int wm = (wid >> 2) * 64, wn = (wid & 3) * 32;

    float c[4][4][4];
#pragma unroll
    for (int mt = 0; mt < 4; mt++)
#pragma unroll
        for (int nt = 0; nt < 4; nt++)
#pragma unroll
            for (int r = 0; r < 4; r++) c[mt][nt][r] = 0.f;

    for (int ch = 0; ch < 4; ch++){
#pragma unroll
        for (int it = 0; it < 4; it++){
            int i = it*256 + tid;
            int row = i >> 3, pg = (i & 7)*4;
            size_t ga = (size_t)(t0 + row)*128 + ch*32 + pg;
            size_t gb = (size_t)(wsel*32768) + (or0 + row)*128 + ch*32 + pg;
            u32 off = (u32)(row*PITCHB + pg*4);
            *(uint4*)(sm + SA_H + off) = *(const uint4*)&g_xh[ga];
            *(uint4*)(sm + SA_L + off) = *(const uint4*)&g_xl[ga];
            *(uint4*)(sm + SB_H + off) = *(const uint4*)&g_wh[gb];
            *(uint4*)(sm + SB_L + off) = *(const uint4*)&g_wl[gb];
        }
        __syncthreads();
        mma_chunk(smb, wm, wn, lane, c);
        __syncthreads();
    }

#pragma unroll
    for (int mt = 0; mt < 4; mt++){
#pragma unroll
        for (int nt = 0; nt < 4; nt++){
            int row = t0 + wm + mt*16 + (lane >> 2);
            int col = (or0 + wn + nt*8 + (lane & 3)*2) >> 1;
            u32 h, l;
            f16split2(c[mt][nt][0], c[mt][nt][1], h, l);
            dsth[(size_t)row*128 + col] = h;
            dstl[(size_t)row*128 + col] = l;
            f16split2(c[mt][nt][2], c[mt][nt][3], h, l);
            dsth[(size_t)(row+8)*128 + col] = h;
            dstl[(size_t)(row+8)*128 + col] = l;
        }
    }
}

/* ------------------------------------------------------------------ */
/* K2: global key-dash max per (b,h) — 3-pass fp16 split.              */
/* grid (72, 32), 256 thr.                                             */
/* ------------------------------------------------------------------ */
__global__ void __launch_bounds__(256) k_kmax(){
    __shared__ u32 projh[128*20];
    __shared__ u32 projl[128*20];
    __shared__ u32 kth[128*20];
    __shared__ u32 ktl[128*20];
    __shared__ float red[256];
    int bh = blockIdx.y, b = bh >> 3, h = bh & 7;
    int n0 = blockIdx.x * 128;
    int t = threadIdx.x, wid = t >> 5, lane = t & 31;

    for (int i = t; i < 2048; i += 256){
        projh[(i>>4)*20 + (i&15)] = g_projh[i];
        projl[(i>>4)*20 + (i&15)] = g_projl[i];
    }
    for (int i = t; i < 2048; i += 256){
        int tok = i >> 4, cc = i & 15;
        size_t g = (size_t)(b*NN + n0 + tok)*128 + h*16 + cc;
        kth[tok*20 + cc] = g_kh[g];
        ktl[tok*20 + cc] = g_kl[g];
    }
    __syncthreads();

    int wm = (wid >> 1)*32, wn = (wid & 1)*64;
    float c[2][8][4];
#pragma unroll
    for (int mt = 0; mt < 2; mt++)
#pragma unroll
        for (int nt = 0; nt < 8; nt++)
#pragma unroll
            for (int r = 0; r < 4; r++) c[mt][nt][r] = 0.f;

    u32 smPH = smem_u32(projh), smPL = smem_u32(projl);
    u32 smKH = smem_u32(kth),   smKL = smem_u32(ktl);
    u32 a_off = (u32)((wm + (lane & 15))*80 + (lane >> 4)*16);
    u32 b_off = (u32)((wn + (lane & 7) + ((lane >> 4) & 1)*8)*80 + ((lane >> 3) & 1)*16);
#pragma unroll
    for (int ks = 0; ks < 2; ks++){
        u32 ah[2][4], bh2[4][4];
#pragma unroll
        for (int mt = 0; mt < 2; mt++)
            LDM4(ah[mt], smPH + a_off + mt*(16*80) + ks*32);
#pragma unroll
        for (int np = 0; np < 4; np++)
            LDM4(bh2[np], smKH + b_off + np*(16*80) + ks*32);
#pragma unroll
        for (int mt = 0; mt < 2; mt++)
#pragma unroll
            for (int nt = 0; nt < 8; nt++)
                MMA16816(c[mt][nt], ah[mt], bh2[nt>>1][(nt&1)*2], bh2[nt>>1][(nt&1)*2+1]);
        {
            u32 bl[4][4];
#pragma unroll
            for (int np = 0; np < 4; np++)
                LDM4(bl[np], smKL + b_off + np*(16*80) + ks*32);
#pragma unroll
            for (int mt = 0; mt < 2; mt++)
#pragma unroll
                for (int nt = 0; nt < 8; nt++)
                    MMA16816(c[mt][nt], ah[mt], bl[nt>>1][(nt&1)*2], bl[nt>>1][(nt&1)*2+1]);
        }
        {
            u32 al[2][4];
#pragma unroll
            for (int mt = 0; mt < 2; mt++)
                LDM4(al[mt], smPL + a_off + mt*(16*80) + ks*32);
#pragma unroll
            for (int mt = 0; mt < 2; mt++)
#pragma unroll
                for (int nt = 0; nt < 8; nt++)
                    MMA16816(c[mt][nt], al[mt], bh2[nt>>1][(nt&1)*2], bh2[nt>>1][(nt&1)*2+1]);
        }
    }
    float mx = -1e30f;
#pragma unroll
    for (int mt = 0; mt < 2; mt++)
#pragma unroll
        for (int nt = 0; nt < 8; nt++)
#pragma unroll
            for (int r = 0; r < 4; r++) mx = fmaxf(mx, c[mt][nt][r]);
    red[t] = mx;
    __syncthreads();
    for (int s = 128; s > 0; s >>= 1){
        if (t < (unsigned)s) red[t] = fmaxf(red[t], red[t + s]);
        __syncthreads();
    }
    if (t == 0) atomicMaxF(&g_kmax[bh], red[0]);
}

/* ------------------------------------------------------------------ */
/* K3: fused key features + ctx. grid (16, 32), 256 thr.               */
/* ------------------------------------------------------------------ */
#define CP_PROJH 0
#define CP_PROJL 10240
#define CP_KTH   20480
#define CP_KTL   25600
#define CP_KPSH  30720
#define CP_KPSL  49152
#define CP_VTH   67584
#define CP_VTL   74496
#define CP_VSGH  81408
#define CP_VSGL  85504
#define CP_DIAG  89600
#define CTX_SMEM 89856
#define CTX_SPLITS 16
#define CTX_TILES  9

__global__ void __launch_bounds__(256) k_ctx2(){
    extern __shared__ char sm[];
    u32 smb = smem_u32(sm);
    int bh = blockIdx.y, b = bh >> 3, h = bh & 7;
    int sp = blockIdx.x;
    int t = threadIdx.x, wid = t >> 5, lane = t & 31;
    float gmax = g_kmax[bh];

    u32* PJH = (u32*)(sm + CP_PROJH); u32* PJL = (u32*)(sm + CP_PROJL);
    u32* KTH = (u32*)(sm + CP_KTH);   u32* KTL = (u32*)(sm + CP_KTL);
    u32* VTH = (u32*)(sm + CP_VTH);   u32* VTL = (u32*)(sm + CP_VTL);
    u32* VSH = (u32*)(sm + CP_VSGH);  u32* VSL = (u32*)(sm + CP_VSGL);
    float* DIAG = (float*)(sm + CP_DIAG);

    for (int i = t; i < 2048; i += 256){
        PJH[(i>>4)*20 + (i&15)] = g_projh[i];
        PJL[(i>>4)*20 + (i&15)] = g_projl[i];
    }
    for (int i = t; i < 1024; i += 256){
        int mat = i >> 9, rem = i & 511;
        int j = 32 + (rem >> 5), tp = rem & 31;
        u32 v = (j == 32 && mat == 0) ? 0x3C003C00u : 0u;
        ((mat == 0) ? VTH : VTL)[j*36 + tp] = v;
    }

    int wm1 = (wid >> 1)*32, wn1 = (wid & 1)*32;
    u32 a1_off = (u32)((wm1 + (lane & 15))*80 + (lane >> 4)*16);
    u32 b1_off = (u32)((wn1 + (lane & 7) + ((lane >> 4) & 1)*8)*80 + ((lane >> 3) & 1)*16);
    int wm2 = (wid >> 1)*32, wn2 = (wid & 1)*24;
    u32 a2_off = (u32)((wm2 + (lane & 15))*144 + (lane >> 4)*16);
    u32 b2_off = (u32)((wn2 + (lane & 7) + ((lane >> 4) & 1)*8)*144 + ((lane >> 3) & 1)*16);

    float c2[2][3][4];
#pragma unroll
    for (int mt = 0; mt < 2; mt++)
#pragma unroll
        for (int nt = 0; nt < 3; nt++)
#pragma unroll
            for (int r = 0; r < 4; r++) c2[mt][nt][r] = 0.f;

    for (int it = 0; it < CTX_TILES; it++){
        int n0 = sp*(CTX_TILES*64) + it*64;
        for (int i = t; i < 1024; i += 256){
            int tok = i >> 4, cc = i & 15;
            size_t g = (size_t)(b*NN + n0 + tok)*128 + h*16 + cc;
            KTH[tok*20 + cc] = g_kh[g];
            KTL[tok*20 + cc] = g_kl[g];
            VSH[tok*16 + cc] = g_vh[g];
            VSL[tok*16 + cc] = g_vl[g];
        }
        __syncthreads();
        if (t < 64){
            float sq = 0.f;
#pragma unroll
            for (int i = 0; i < 16; i++){
                float2 v = h2f(KTH[t*20 + i], KTL[t*20 + i]);
                sq += v.x*v.x + v.y*v.y;
            }
            DIAG[t] = HALF_NRM2 * sq;
        }
        for (int i = t; i < 2048; i += 256){
            int mat = i >> 10, rem = i & 1023;
            int j = rem >> 5, tp = rem & 31;
            int tok0 = tp*2;
            u32* src = mat ? VSL : VSH;
            u32 w0 = src[tok0*16 + (j >> 1)];
            u32 w1 = src[(tok0+1)*16 + (j >> 1)];
            u32 h0 = (j & 1) ? (w0 >> 16) : (w0 & 0xFFFF);
            u32 h1 = (j & 1) ? (w1 >> 16) : (w1 & 0xFFFF);
            (mat ? VTL : VTH)[j*36 + tp] = h0 | (h1 << 16);
        }
        __syncthreads();

        float c1[2][4][4];
#pragma unroll
        for (int mt = 0; mt < 2; mt++)
#pragma unroll
            for (int nt = 0; nt < 4; nt++)
#pragma unroll
                for (int r = 0; r < 4; r++) c1[mt][nt][r] = 0.f;
#pragma unroll
        for (int ks = 0; ks < 2; ks++){
            u32 ah[2][4], bhh[2][4];
#pragma unroll
            for (int mt = 0; mt < 2; mt++)
                LDM4(ah[mt], smb + CP_PROJH + a1_off + mt*(16*80) + ks*32);
#pragma unroll
            for (int np = 0; np < 2; np++)
                LDM4(bhh[np], smb + CP_KTH + b1_off + np*(16*80) + ks*32);
#pragma unroll
            for (int mt = 0; mt < 2; mt++)
#pragma unroll
                for (int nt = 0; nt < 4; nt++)
                    MMA16816(c1[mt][nt], ah[mt], bhh[nt>>1][(nt&1)*2], bhh[nt>>1][(nt&1)*2+1]);
            {
                u32 bl[2][4];
#pragma unroll
                for (int np = 0; np < 2; np++)
                    LDM4(bl[np], smb + CP_KTL + b1_off + np*(16*80) + ks*32);
#pragma unroll
                for (int mt = 0; mt < 2; mt++)
#pragma unroll
                    for (int nt = 0; nt < 4; nt++)
                        MMA16816(c1[mt][nt], ah[mt], bl[nt>>1][(nt&1)*2], bl[nt>>1][(nt&1)*2+1]);
            }
            {
                u32 al[2][4];
#pragma unroll
                for (int mt = 0; mt < 2; mt++)
                    LDM4(al[mt], smb + CP_PROJL + a1_off + mt*(16*80) + ks*32);
#pragma unroll
                for (int mt = 0; mt < 2; mt++)
#pragma unroll
                    for (int nt = 0; nt < 4; nt++)
                        MMA16816(c1[mt][nt], al[mt], bhh[nt>>1][(nt&1)*2], bhh[nt>>1][(nt&1)*2+1]);
            }
        }
        u32* KPH = (u32*)(sm + CP_KPSH);
        u32* KPL = (u32*)(sm + CP_KPSL);
#pragma unroll
        for (int mt = 0; mt < 2; mt++){
#pragma unroll
            for (int nt = 0; nt < 4; nt++){
                int col = wn1 + nt*8 + (lane & 3)*2;
                float d0 = DIAG[col] + gmax, d1 = DIAG[col+1] + gmax;
                int r0 = wm1 + mt*16 + (lane >> 2);
                float v0 = KP_RATIO*(__expf(c1[mt][nt][0] - d0) + EPSF);
                float v1 = KP_RATIO*(__expf(c1[mt][nt][1] - d1) + EPSF);
                float v2 = KP_RATIO*(__expf(c1[mt][nt][2] - d0) + EPSF);
                float v3 = KP_RATIO*(__expf(c1[mt][nt][3] - d1) + EPSF);
                u32 hh, ll;
                f16split2(v0, v1, hh, ll);
                KPH[r0*36 + (col>>1)] = hh; KPL[r0*36 + (col>>1)] = ll;
                f16split2(v2, v3, hh, ll);
                KPH[(r0+8)*36 + (col>>1)] = hh; KPL[(r0+8)*36 + (col>>1)] = ll;
            }
        }
        __syncthreads();

#pragma unroll
        for (int ks = 0; ks < 4; ks++){
            u32 ah[2][4], bhh[2][4];
#pragma unroll
            for (int mt = 0; mt < 2; mt++)
                LDM4(ah[mt], smb + CP_KPSH + a2_off + mt*(16*144) + ks*32);
#pragma unroll
            for (int np = 0; np < 2; np++)
                LDM4(bhh[np], smb + CP_VTH + b2_off + np*(16*144) + ks*32);
#pragma unroll
            for (int mt = 0; mt < 2; mt++)
#pragma unroll
                for (int nt = 0; nt < 3; nt++)
                    MMA16816(c2[mt][nt], ah[mt], bhh[nt>>1][(nt&1)*2], bhh[nt>>1][(nt&1)*2+1]);
            {
                u32 bl[2][4];
#pragma unroll
                for (int np = 0; np < 2; np++)
                    LDM4(bl[np], smb + CP_VTL + b2_off + np*(16*144) + ks*32);
#pragma unroll
                for (int mt = 0; mt < 2; mt++)
#pragma unroll
                    for (int nt = 0; nt < 3; nt++)
                        MMA16816(c2[mt][nt], ah[mt], bl[nt>>1][(nt&1)*2], bl[nt>>1][(nt&1)*2+1]);
            }
            {
                u32 al[2][4];
#pragma unroll
                for (int mt = 0; mt < 2; mt++)
                    LDM4(al[mt], smb + CP_KPSL + a2_off + mt*(16*144) + ks*32);
#pragma unroll
                for (int mt = 0; mt < 2; mt++)
#pragma unroll
                    for (int nt = 0; nt < 3; nt++)
                        MMA16816(c2[mt][nt], al[mt], bhh[nt>>1][(nt&1)*2], bhh[nt>>1][(nt&1)*2+1]);
            }
        }
        __syncthreads();
    }

#pragma unroll
    for (int mt = 0; mt < 2; mt++){
#pragma unroll
        for (int nt = 0; nt < 3; nt++){
            int m = wm2 + mt*16 + (lane >> 2);
            int n = wn2 + nt*8 + (lane & 3)*2;
            size_t base = ((size_t)bh*MF + m)*33;
            if (n < 33)   atomicAdd(&g_ctx[base + n],     c2[mt][nt][0]);
            if (n+1 < 33) atomicAdd(&g_ctx[base + n + 1], c2[mt][nt][1]);
            if (n < 33)   atomicAdd(&g_ctx[base + 264 + n],     c2[mt][nt][2]);
            if (n+1 < 33) atomicAdd(&g_ctx[base + 264 + n + 1], c2[mt][nt][3]);
        }
    }
}

/* ------------------------------------------------------------------ */
/* K4: fused query features + qp@ctx + d_inv. grid (144, 32), 256 thr. */
/* ------------------------------------------------------------------ */
#define QP_PROJH 0
#define QP_PROJL 10240
#define QP_QTH   20480
#define QP_QTL   25600
#define QP_QPSH  30720
#define QP_QPSL  49152
#define QP_CTH   67584
#define QP_CTL   84992
#define QP_PM    102400
#define QP_RMAX  103424
#define QP_DIAG  103680
#define QP_STG   QP_QPSH
#define QA_SMEM  103936

__global__ void __launch_bounds__(256) k_qattn2(){
    extern __shared__ char sm[];
    u32 smb = smem_u32(sm);
    int bh = blockIdx.y, b = bh >> 3, h = bh & 7;
    int n0 = blockIdx.x * 64;
    int t = threadIdx.x, wid = t >> 5, lane = t & 31;

    u32* PJH = (u32*)(sm + QP_PROJH); u32* PJL = (u32*)(sm + QP_PROJL);
    u32* QTH = (u32*)(sm + QP_QTH);   u32* QTL = (u32*)(sm + QP_QTL);
    u32* CTH = (u32*)(sm + QP_CTH);   u32* CTL = (u32*)(sm + QP_CTL);
    float* PM = (float*)(sm + QP_PM);
    float* RMAX = (float*)(sm + QP_RMAX);
    float* DIAG = (float*)(sm + QP_DIAG);

    for (int i = t; i < 2048; i += 256){
        PJH[(i>>4)*20 + (i&15)] = g_projh[i];
        PJL[(i>>4)*20 + (i&15)] = g_projl[i];
    }
    for (int i = t; i < 1024; i += 256){
        int tok = i >> 4, cc = i & 15;
        size_t g = (size_t)(b*NN + n0 + tok)*128 + h*16 + cc;
        QTH[tok*20 + cc] = g_qh[g];
        QTL[tok*20 + cc] = g_ql[g];
    }
    for (int i = t; i < 4096; i += 256){
        int j = i >> 6, mp = i & 63;
        float a = 0.f, bb = 0.f;
        if (j < 33){
            a  = g_ctx[((size_t)bh*MF + mp*2)*33 + j];
            bb = g_ctx[((size_t)bh*MF + mp*2 + 1)*33 + j];
        }
        u32 hh, ll;
        f16split2(a, bb, hh, ll);
        CTH[j*68 + mp] = hh; CTL[j*68 + mp] = ll;
    }
    __syncthreads();
    if (t < 64){
        float sq = 0.f;
#pragma unroll
        for (int i = 0; i < 16; i++){
            float2 v = h2f(QTH[t*20 + i], QTL[t*20 + i]);
            sq += v.x*v.x + v.y*v.y;
        }
        DIAG[t] = HALF_NRM2 * sq;
    }
    __syncthreads();

    int wm1 = (wid >> 1)*32, wn1 = (wid & 1)*32;
    u32 a1_off = (u32)((wm1 + (lane & 15))*80 + (lane >> 4)*16);
    u32 b1_off = (u32)((wn1 + (lane & 7) + ((lane >> 4) & 1)*8)*80 + ((lane >> 3) & 1)*16);
    float c1[2][4][4];
#pragma unroll
    for (int mt = 0; mt < 2; mt++)
#pragma unroll
        for (int nt = 0; nt < 4; nt++)
#pragma unroll
            for (int r = 0; r < 4; r++) c1[mt][nt][r] = 0.f;
#pragma unroll
    for (int ks = 0; ks < 2; ks++){
        u32 ah[2][4], bhh[2][4];
#pragma unroll
        for (int mt = 0; mt < 2; mt++)
            LDM4(ah[mt], smb + QP_PROJH + a1_off + mt*(16*80) + ks*32);
#pragma unroll
        for (int np = 0; np < 2; np++)
            LDM4(bhh[np], smb + QP_QTH + b1_off + np*(16*80) + ks*32);
#pragma unroll
        for (int mt = 0; mt < 2; mt++)
#pragma unroll
            for (int nt = 0; nt < 4; nt++)
                MMA16816(c1[mt][nt], ah[mt], bhh[nt>>1][(nt&1)*2], bhh[nt>>1][(nt&1)*2+1]);
        {
            u32 bl[2][4];
#pragma unroll
            for (int np = 0; np < 2; np++)
                LDM4(bl[np], smb + QP_QTL + b1_off + np*(16*80) + ks*32);
#pragma unroll
            for (int mt = 0; mt < 2; mt++)
#pragma unroll
                for (int nt = 0; nt < 4; nt++)
                    MMA16816(c1[mt][nt], ah[mt], bl[nt>>1][(nt&1)*2], bl[nt>>1][(nt&1)*2+1]);
        }
        {
            u32 al[2][4];
#pragma unroll
            for (int mt = 0; mt < 2; mt++)
                LDM4(al[mt], smb + QP_PROJL + a1_off + mt*(16*80) + ks*32);
#pragma unroll
            for (int mt = 0; mt < 2; mt++)
#pragma unroll
                for (int nt = 0; nt < 4; nt++)
                    MMA16816(c1[mt][nt], al[mt], bhh[nt>>1][(nt&1)*2], bhh[nt>>1][(nt&1)*2+1]);
        }
    }

#pragma unroll
    for (int nt = 0; nt < 4; nt++){
        float me = fmaxf(fmaxf(c1[0][nt][0], c1[0][nt][2]),
                         fmaxf(c1[1][nt][0], c1[1][nt][2]));
        float mo = fmaxf(fmaxf(c1[0][nt][1], c1[0][nt][3]),
                         fmaxf(c1[1][nt][1], c1[1][nt][3]));
#pragma unroll
        for (int s = 4; s < 32; s <<= 1){
            me = fmaxf(me, __shfl_xor_sync(0xFFFFFFFF, me, s));
            mo = fmaxf(mo, __shfl_xor_sync(0xFFFFFFFF, mo, s));
        }
        if ((lane >> 2) == 0){
            int col = wn1 + nt*8 + (lane & 3)*2;
            PM[(wid >> 1)*64 + col]     = me;
            PM[(wid >> 1)*64 + col + 1] = mo;
        }
    }
    __syncthreads();
    if (t < 64){
        float mx = PM[t];
        mx = fmaxf(mx, PM[64 + t]);
        mx = fmaxf(mx, PM[128 + t]);
        mx = fmaxf(mx, PM[192 + t]);
        RMAX[t] = mx;
    }
    __syncthreads();

    {
        u32* QPH = (u32*)(sm + QP_QPSH);
        u32* QPL = (u32*)(sm + QP_QPSL);
#pragma unroll
        for (int mt = 0; mt < 2; mt++){
#pragma unroll
            for (int nt = 0; nt < 4; nt++){
                int col = wn1 + nt*8 + (lane & 3)*2;
                float d0 = DIAG[col] + RMAX[col], d1 = DIAG[col+1] + RMAX[col+1];
                int r0 = wm1 + mt*16 + (lane >> 2);
                float v0 = QP_RATIO*(__expf(c1[mt][nt][0] - d0) + EPSF);
                float v1 = QP_RATIO*(__expf(c1[mt][nt][1] - d1) + EPSF);
                float v2 = QP_RATIO*(__expf(c1[mt][nt][2] - d0) + EPSF);
                float v3 = QP_RATIO*(__expf(c1[mt][nt][3] - d1) + EPSF);
                u32 hh, ll;
                f16split2(v0, v1, hh, ll);
                QPH[r0*36 + (col>>1)] = hh; QPL[r0*36 + (col>>1)] = ll;
                f16split2(v2, v3, hh, ll);
                QPH[(r0+8)*36 + (col>>1)] = hh; QPL[(r0+8)*36 + (col>>1)] = ll;
            }
        }
    }
    __syncthreads();

    int wm2 = (wid >> 1)*16, wn2 = (wid & 1)*32;
    u32 a2_off = (u32)((wm2 + (lane & 15))*272 + (lane >> 4)*16);
    float c2[4][4];
#pragma unroll
    for (int nt = 0; nt < 4; nt++)
#pragma unroll
        for (int r = 0; r < 4; r++) c2[nt][r] = 0.f;
#pragma unroll
    for (int ks = 0; ks < 8; ks++){
        u32 ah[4], al[4], bt[2][4], btl[2][4];
        LDM4(ah, smb + QP_CTH + a2_off + ks*32);
        LDM4(al, smb + QP_CTL + a2_off + ks*32);
        u32 rowb = (u32)((ks*16 + (lane & 7) + ((lane >> 3) & 1)*8)*144);
#pragma unroll
        for (int np = 0; np < 2; np++){
            u32 colb = (u32)((wn2 + np*16 + ((lane >> 4) & 1)*8)*2);
            LDM4T(bt[np],  smb + QP_QPSH + rowb + colb);
            LDM4T(btl[np], smb + QP_QPSL + rowb + colb);
        }
#pragma unroll
        for (int nt = 0; nt < 4; nt++){
            MMA16816(c2[nt], ah, bt[nt>>1][(nt&1)*2],  bt[nt>>1][(nt&1)*2+1]);
            MMA16816(c2[nt], ah, btl[nt>>1][(nt&1)*2], btl[nt>>1][(nt&1)*2+1]);
            MMA16816(c2[nt], al, bt[nt>>1][(nt&1)*2],  bt[nt>>1][(nt&1)*2+1]);
        }
    }
    __syncthreads();

    float* STG = (float*)(sm + QP_STG);
#pragma unroll
    for (int nt = 0; nt < 4; nt++){
        int j = wm2 + (lane >> 2);
        int tok = wn2 + nt*8 + (lane & 3)*2;
        if (j <= 32){
            STG[j*68 + tok]     = c2[nt][0];
            STG[j*68 + tok + 1] = c2[nt][1];
        }
        if (j + 8 <= 32){
            STG[(j+8)*68 + tok]     = c2[nt][2];
            STG[(j+8)*68 + tok + 1] = c2[nt][3];
        }
    }
    __syncthreads();

    /* write attn as fp16 hi/lo pairs */
    {
        int tok = t >> 2, jb = (t & 3)*8;
        float inv = 1.0f / STG[32*68 + tok];
        u32 hv[4], lv[4];
#pragma unroll
        for (int p = 0; p < 4; p++){
            float v0 = STG[(jb + 2*p)*68 + tok] * inv;
            float v1 = STG[(jb + 2*p + 1)*68 + tok] * inv;
            f16split2(v0, v1, hv[p], lv[p]);
        }
        size_t base = (size_t)(b*NN + n0 + tok)*128 + h*16 + (jb >> 1);
        *(uint4*)&g_ah[base] = make_uint4(hv[0], hv[1], hv[2], hv[3]);
        *(uint4*)&g_al[base] = make_uint4(lv[0], lv[1], lv[2], lv[3]);
    }
}

/* ------------------------------------------------------------------ */
/* K5: final GEMM — pure fp16 copies + mma. grid (2, 288), 256 thr.    */
/* ------------------------------------------------------------------ */
__global__ void __launch_bounds__(256, 2) k_final_t(float* __restrict__ out){
    extern __shared__ char sm[];
    u32 smb = smem_u32(sm);
    int tid = threadIdx.x, wid = tid >> 5, lane = tid & 31;
    int o0 = blockIdx.x * 128;
    int t0 = blockIdx.y * 128;
    int b = t0 / NN, tl0 = t0 % NN;

    int wm = (wid >> 2) * 64, wn = (wid & 3) * 32;

    float c[4][4][4];
#pragma unroll
    for (int mt = 0; mt < 4; mt++)
#pragma unroll
        for (int nt = 0; nt < 4; nt++)
#pragma unroll
            for (int r = 0; r < 4; r++) c[mt][nt][r] = 0.f;

    for (int ch = 0; ch < 4; ch++){
#pragma unroll
        for (int it = 0; it < 4; it++){
            int i = it*256 + tid;
            int row = i >> 3, pg = (i & 7)*4;
            size_t ga = (size_t)(t0 + row)*128 + ch*32 + pg;
            size_t gb = (size_t)(o0 + row)*128 + ch*32 + pg;
            u32 off = (u32)(row*PITCHB + pg*4);
            *(uint4*)(sm + SA_H + off) = *(const uint4*)&g_ah[ga];
            *(uint4*)(sm + SA_L + off) = *(const uint4*)&g_al[ga];
            *(uint4*)(sm + SB_H + off) = *(const uint4*)&g_wch[gb];
            *(uint4*)(sm + SB_L + off) = *(const uint4*)&g_wcl[gb];
        }
        __syncthreads();
        mma_chunk(smb, wm, wn, lane, c);
        __syncthreads();
    }

    float* stage = (float*)sm;
#pragma unroll
    for (int mt = 0; mt < 4; mt++){
#pragma unroll
        for (int nt = 0; nt < 4; nt++){
            int r = wm + mt*16 + (lane >> 2);
            int cc = wn + nt*8 + (lane & 3)*2;
            stage[cc*132 + r]         = c[mt][nt][0];
            stage[(cc+1)*132 + r]     = c[mt][nt][1];
            stage[cc*132 + r + 8]     = c[mt][nt][2];
            stage[(cc+1)*132 + r + 8] = c[mt][nt][3];
        }
    }
    __syncthreads();
#pragma unroll
    for (int i2 = 0; i2 < 16; i2++){
        int idx = i2*256 + tid;
        int cc = idx >> 5, t4 = (idx & 31) * 4;
        int o = o0 + cc;
        float bias = g_bc[o];
        float4 v = *(float4*)&stage[cc*132 + t4];
        v.x += bias; v.y += bias; v.z += bias; v.w += bias;
        *(float4*)&out[((size_t)b*256 + o)*NN + tl0 + t4] = v;
    }
}

/* ------------------------------------------------------------------ */
extern "C" void kernel_launch(void* const* d_in, const int* in_sizes, int n_in,
                              void* d_out, int out_size){
    const float* x    = (const float*)d_in[0];
    const float* wq   = (const float*)d_in[1];
    const float* wk   = (const float*)d_in[2];
    const float* wv   = (const float*)d_in[3];
    const float* wo   = (const float*)d_in[4];
    const float* bo   = (const float*)d_in[5];
    const float* proj = (const float*)d_in[6];
    const float* wp   = (const float*)d_in[7];
    const float* bp   = (const float*)d_in[8];
    float* out = (float*)d_out;

    cudaFuncSetAttribute(k_qkv_t,   cudaFuncAttributeMaxDynamicSharedMemorySize, G2_SMEM);
    cudaFuncSetAttribute(k_final_t, cudaFuncAttributeMaxDynamicSharedMemorySize, G2_SMEM);
    cudaFuncSetAttribute(k_ctx2,    cudaFuncAttributeMaxDynamicSharedMemorySize, CTX_SMEM);
    cudaFuncSetAttribute(k_qattn2,  cudaFuncAttributeMaxDynamicSharedMemorySize, QA_SMEM);

    k_prep<<<256, 256>>>(wo, bo, wp, bp);
    k_prep_proj<<<8, 256>>>(proj);
    k_prep_w<<<384, 256>>>(wq, wk, wv);
    k_prep_wc<<<128, 256>>>();
    k_init<<<(32*MF*33 + 255)/256, 256>>>();
    k_xcvt<<<TT/128, 256>>>(x);
    k_qkv_t<<<dim3(6, TT/128), 256, G2_SMEM>>>();
    k_kmax<<<dim3(NN/128, 32), 256>>>();
    k_ctx2<<<dim3(CTX_SPLITS, 32), 256, CTX_SMEM>>>();
    k_qattn2<<<dim3(NN/64, 32), 256, QA_SMEM>>>();
    k_final_t<<<dim3(2, TT/128), 256, G2_SMEM>>>(out);
}